// round 6
// baseline (speedup 1.0000x reference)
#include <cuda_runtime.h>

// ---------------- problem constants ----------------
#define T_TOKENS 16384      // b*s = 4*4096
#define SEQ      4096
#define DIM      2048
#define QLORA    1536
#define NH       16
#define DN       128
#define DR       64
#define DV       128
#define KVL      512
#define HD       192        // DN+DR
#define QDIM     3072       // NH*HD
#define KVA      576        // KVL+DR
#define KVUPD    4096       // NH*(DN+DV)

// ---------------- scratch (no allocs allowed) ----------------
__device__ float g_qa  [(size_t)T_TOKENS * QLORA];
__device__ float g_q   [(size_t)T_TOKENS * QDIM];
__device__ float g_kv  [(size_t)T_TOKENS * KVA];
__device__ float g_kvn [(size_t)T_TOKENS * KVL];
__device__ float g_kvup[(size_t)T_TOKENS * KVUPD];
__device__ float g_ctx [(size_t)T_TOKENS * (NH * DV)];

// ---------------- packed f32x2 helpers ----------------
__device__ __forceinline__ unsigned long long pack_dup(float a) {
    unsigned long long r;
    unsigned int ai = __float_as_uint(a);
    asm("mov.b64 %0, {%1, %1};" : "=l"(r) : "r"(ai));
    return r;
}
__device__ __forceinline__ void fma2(unsigned long long& c,
                                     unsigned long long a,
                                     unsigned long long b) {
    asm("fma.rn.f32x2 %0, %1, %2, %0;" : "+l"(c) : "l"(a), "l"(b));
}

// ---------------- SGEMM: C[M,N] = A[M,K] @ B[K,N], row-major ----------------
// BM=BN=128, BK=16, 256 threads, 8x8 per-thread, f32x2 packed accumulation.
// Requires: M % 128 == 0, K % 16 == 0, N % 8 == 0 (N may be non-mult of 128).
__global__ __launch_bounds__(256, 2)
void sgemm_kernel(const float* __restrict__ A, const float* __restrict__ B,
                  float* __restrict__ C, int M, int N, int K)
{
    __shared__ float As[16][132];   // transposed A tile, pad 4 for bank spread
    __shared__ float Bs[16][128];

    const int tid = threadIdx.x;
    const int tx  = tid & 15;       // n-direction (8 cols each)
    const int ty  = tid >> 4;       // m-direction (8 rows each)
    const int m0  = blockIdx.y << 7;
    const int n0  = blockIdx.x << 7;

    const int a_row = tid >> 2;          // 0..63  (x2 iterations)
    const int a_col = (tid & 3) << 2;    // 0,4,8,12
    const int b_row = tid >> 5;          // 0..7   (x2 iterations)
    const int b_col = (tid & 31) << 2;   // 0..124

    unsigned long long c2[8][4];
    #pragma unroll
    for (int i = 0; i < 8; i++)
        #pragma unroll
        for (int j = 0; j < 4; j++) c2[i][j] = 0ULL;

    for (int k0 = 0; k0 < K; k0 += 16) {
        #pragma unroll
        for (int r = 0; r < 2; r++) {
            int row = a_row + 64 * r;
            float4 av = *(const float4*)(A + (size_t)(m0 + row) * K + (k0 + a_col));
            As[a_col + 0][row] = av.x;
            As[a_col + 1][row] = av.y;
            As[a_col + 2][row] = av.z;
            As[a_col + 3][row] = av.w;
        }
        #pragma unroll
        for (int r = 0; r < 2; r++) {
            int row = b_row + 8 * r;
            int col = n0 + b_col;
            float4 bv = make_float4(0.f, 0.f, 0.f, 0.f);
            if (col < N)
                bv = *(const float4*)(B + (size_t)(k0 + row) * N + col);
            *(float4*)(&Bs[row][b_col]) = bv;
        }
        __syncthreads();

        #pragma unroll
        for (int k = 0; k < 16; k++) {
            float a[8];
            *(float4*)(&a[0]) = *(const float4*)(&As[k][ty * 8]);
            *(float4*)(&a[4]) = *(const float4*)(&As[k][ty * 8 + 4]);
            unsigned long long b2[4];
            const unsigned long long* bp =
                (const unsigned long long*)(&Bs[k][tx * 8]);
            #pragma unroll
            for (int j = 0; j < 4; j++) b2[j] = bp[j];
            #pragma unroll
            for (int i = 0; i < 8; i++) {
                unsigned long long a2 = pack_dup(a[i]);
                #pragma unroll
                for (int j = 0; j < 4; j++) fma2(c2[i][j], a2, b2[j]);
            }
        }
        __syncthreads();
    }

    const int col = n0 + tx * 8;
    if (col < N) {
        #pragma unroll
        for (int i = 0; i < 8; i++) {
            int row = m0 + ty * 8 + i;
            float2 f0 = *(float2*)&c2[i][0];
            float2 f1 = *(float2*)&c2[i][1];
            float2 f2 = *(float2*)&c2[i][2];
            float2 f3 = *(float2*)&c2[i][3];
            *(float4*)(C + (size_t)row * N + col)     = make_float4(f0.x, f0.y, f1.x, f1.y);
            *(float4*)(C + (size_t)row * N + col + 4) = make_float4(f2.x, f2.y, f3.x, f3.y);
        }
    }
}

// ---------------- RMSNorm (block per row) ----------------
__global__ void rmsnorm_kernel(const float* __restrict__ in, float* __restrict__ out,
                               const float* __restrict__ w, int len,
                               int in_stride, int out_stride)
{
    const int row = blockIdx.x;
    const float* ip = in + (size_t)row * in_stride;
    float* op = out + (size_t)row * out_stride;

    float ss = 0.f;
    for (int i = threadIdx.x; i < len; i += blockDim.x) {
        float v = ip[i];
        ss += v * v;
    }
    __shared__ float red[256];
    red[threadIdx.x] = ss;
    __syncthreads();
    #pragma unroll
    for (int s = 128; s > 0; s >>= 1) {
        if (threadIdx.x < s) red[threadIdx.x] += red[threadIdx.x + s];
        __syncthreads();
    }
    const float r = rsqrtf(red[0] / (float)len + 1e-6f);
    for (int i = threadIdx.x; i < len; i += blockDim.x) {
        float v = ip[i] * r;
        if (w) v *= w[i];
        op[i] = v;
    }
}

// ---------------- RoPE on q ----------------
// Reference quirk: q_rope is RESHAPED (b,s,h,dr)->(b,h,s,dr), so the effective
// rope position for original (s,h) is ((s*16 + h) mod 4096) + start_pos.
__global__ void rope_q_kernel(float* __restrict__ q, const int* __restrict__ start_pos)
{
    int idx = blockIdx.x * blockDim.x + threadIdx.x;
    if (idx >= T_TOKENS * NH * 32) return;
    const int i = idx & 31;
    const int h = (idx >> 5) & 15;
    const int t = idx >> 9;
    const int s = t & (SEQ - 1);
    const int pos = ((s * NH + h) & (SEQ - 1)) + start_pos[0];

    const float theta = powf(10000.0f, -(float)i * (1.0f / 32.0f));
    const float ang = (float)pos * theta;
    float sn, cs;
    sincosf(ang, &sn, &cs);

    float* base = q + (size_t)t * QDIM + h * HD + DN;
    const float x1 = base[i];
    const float x2 = base[i + 32];
    base[i]      = x1 * cs - x2 * sn;
    base[i + 32] = x2 * cs + x1 * sn;
}

// ---------------- RoPE on k_pe ----------------
// Reference quirk: k_pe goes through rope() with shape (b,s,1,dr), so
// seq_len==1 and EVERY token uses position == start_pos.
__global__ void rope_k_kernel(float* __restrict__ kv, const int* __restrict__ start_pos)
{
    int idx = blockIdx.x * blockDim.x + threadIdx.x;
    if (idx >= T_TOKENS * 32) return;
    const int i = idx & 31;
    const int t = idx >> 5;
    const int pos = start_pos[0];

    const float theta = powf(10000.0f, -(float)i * (1.0f / 32.0f));
    const float ang = (float)pos * theta;
    float sn, cs;
    sincosf(ang, &sn, &cs);

    float* base = kv + (size_t)t * KVA + KVL;
    const float x1 = base[i];
    const float x2 = base[i + 32];
    base[i]      = x1 * cs - x2 * sn;
    base[i + 32] = x2 * cs + x1 * sn;
}

// ---------------- per-token attention over heads (16x16) ----------------
// scores[qh,kh] = (q[t,qh,:] . k[t,kh,:]) / sqrt(192);  k = [k_nope | k_pe]
// context[t,qh,:] = softmax(scores) @ v
__global__ __launch_bounds__(512)
void attn_kernel(const float* __restrict__ q, const float* __restrict__ kvup,
                 const float* __restrict__ kv, float* __restrict__ ctx)
{
    const int t = blockIdx.x;
    __shared__ float ks[16][HD];   // 16 x 192
    __shared__ float vs[16][DV];   // 16 x 128

    const float* ku = kvup + (size_t)t * KVUPD;
    const float* pe = kv + (size_t)t * KVA + KVL;

    for (int idx = threadIdx.x; idx < 16 * 256; idx += blockDim.x) {
        const int kh = idx >> 8;
        const int c  = idx & 255;
        const float v = ku[idx];
        if (c < DN) ks[kh][c] = v;
        else        vs[kh][c - DN] = v;
    }
    for (int idx = threadIdx.x; idx < 16 * DR; idx += blockDim.x) {
        const int kh = idx >> 6;
        const int c  = idx & 63;
        ks[kh][DN + c] = pe[c];
    }
    __syncthreads();

    const int w    = threadIdx.x >> 5;   // q head
    const int lane = threadIdx.x & 31;
    const float* qr = q + (size_t)t * QDIM + w * HD;

    float qreg[6];
    #pragma unroll
    for (int e = 0; e < 6; e++) qreg[e] = qr[lane + 32 * e];

    float sc[16];
    #pragma unroll
    for (int kh = 0; kh < 16; kh++) {
        float p = 0.f;
        #pragma unroll
        for (int e = 0; e < 6; e++) p += qreg[e] * ks[kh][lane + 32 * e];
        #pragma unroll
        for (int o = 16; o > 0; o >>= 1) p += __shfl_xor_sync(0xffffffffu, p, o);
        sc[kh] = p * 0.07216878364870323f;   // 1/sqrt(192)
    }

    float m = sc[0];
    #pragma unroll
    for (int kh = 1; kh < 16; kh++) m = fmaxf(m, sc[kh]);
    float sum = 0.f;
    #pragma unroll
    for (int kh = 0; kh < 16; kh++) { sc[kh] = expf(sc[kh] - m); sum += sc[kh]; }
    const float inv = 1.f / sum;

    float acc[4] = {0.f, 0.f, 0.f, 0.f};
    #pragma unroll
    for (int kh = 0; kh < 16; kh++) {
        const float p = sc[kh] * inv;
        #pragma unroll
        for (int j = 0; j < 4; j++) acc[j] += p * vs[kh][lane + 32 * j];
    }

    float* o = ctx + (size_t)t * (NH * DV) + w * DV;
    #pragma unroll
    for (int j = 0; j < 4; j++) o[lane + 32 * j] = acc[j];
}

// ---------------- launcher ----------------
extern "C" void kernel_launch(void* const* d_in, const int* in_sizes, int n_in,
                              void* d_out, int out_size)
{
    const float* x        = (const float*)d_in[0];
    const float* wq_a     = (const float*)d_in[1];
    const float* q_norm_w = (const float*)d_in[2];
    const float* wq_b     = (const float*)d_in[3];
    const float* wkv_a    = (const float*)d_in[4];
    const float* wkv_b    = (const float*)d_in[5];
    const float* wo       = (const float*)d_in[6];
    const int*   start_pos = (const int*)d_in[7];
    float* out = (float*)d_out;

    float *qa, *qb, *kvb, *kvn, *kvup, *ctx;
    cudaGetSymbolAddress((void**)&qa,   g_qa);
    cudaGetSymbolAddress((void**)&qb,   g_q);
    cudaGetSymbolAddress((void**)&kvb,  g_kv);
    cudaGetSymbolAddress((void**)&kvn,  g_kvn);
    cudaGetSymbolAddress((void**)&kvup, g_kvup);
    cudaGetSymbolAddress((void**)&ctx,  g_ctx);

    const int MT = T_TOKENS / 128;   // 128 m-tiles

    // 1) q_a = x @ wq_a            [16384,2048] x [2048,1536]
    sgemm_kernel<<<dim3(QLORA / 128, MT), 256>>>(x, wq_a, qa, T_TOKENS, QLORA, DIM);
    // 2) rmsnorm(q_a) * q_norm_w   (in place)
    rmsnorm_kernel<<<T_TOKENS, 256>>>(qa, qa, q_norm_w, QLORA, QLORA, QLORA);
    // 3) q = q_a @ wq_b            [16384,1536] x [1536,3072]
    sgemm_kernel<<<dim3(QDIM / 128, MT), 256>>>(qa, wq_b, qb, T_TOKENS, QDIM, QLORA);
    // 4) kv = x @ wkv_a            [16384,2048] x [2048,576]  (N=576 -> 5 n-tiles)
    sgemm_kernel<<<dim3((KVA + 127) / 128, MT), 256>>>(x, wkv_a, kvb, T_TOKENS, KVA, DIM);
    // 5) RoPE
    rope_q_kernel<<<(T_TOKENS * NH * 32 + 255) / 256, 256>>>(qb, start_pos);
    rope_k_kernel<<<(T_TOKENS * 32 + 255) / 256, 256>>>(kvb, start_pos);
    // 6) kv_c rmsnorm (weight = 1) -> kvn
    rmsnorm_kernel<<<T_TOKENS, 256>>>(kvb, kvn, nullptr, KVL, KVA, KVL);
    // 7) kv_up = kvn @ wkv_b       [16384,512] x [512,4096]
    sgemm_kernel<<<dim3(KVUPD / 128, MT), 256>>>(kvn, wkv_b, kvup, T_TOKENS, KVUPD, KVL);
    // 8) per-token 16x16 attention -> ctx
    attn_kernel<<<T_TOKENS, 512>>>(qb, kvup, kvb, ctx);
    // 9) out = ctx @ wo            [16384,2048] x [2048,2048]
    sgemm_kernel<<<dim3(DIM / 128, MT), 256>>>(ctx, wo, out, T_TOKENS, DIM, DIM);
}

// round 7
// speedup vs baseline: 1.0002x; 1.0002x over previous
#include <cuda_runtime.h>

// ---------------- problem constants ----------------
#define T_TOKENS 16384      // b*s = 4*4096
#define SEQ      4096
#define DIM      2048
#define QLORA    1536
#define NH       16
#define DN       128
#define DR       64
#define DV       128
#define KVL      512
#define HD       192        // DN+DR
#define QDIM     3072       // NH*HD
#define KVA      576        // KVL+DR
#define KVUPD    4096       // NH*(DN+DV)

// ---------------- scratch (no allocs allowed) ----------------
__device__ float g_qa  [(size_t)T_TOKENS * QLORA];
__device__ float g_q   [(size_t)T_TOKENS * QDIM];
__device__ float g_kv  [(size_t)T_TOKENS * KVA];
__device__ float g_kvn [(size_t)T_TOKENS * KVL];
__device__ float g_kvup[(size_t)T_TOKENS * KVUPD];
__device__ float g_ctx [(size_t)T_TOKENS * (NH * DV)];

// ---------------- packed f32x2 helpers ----------------
__device__ __forceinline__ unsigned long long pack_dup(float a) {
    unsigned long long r;
    unsigned int ai = __float_as_uint(a);
    asm("mov.b64 %0, {%1, %1};" : "=l"(r) : "r"(ai));
    return r;
}
__device__ __forceinline__ void fma2(unsigned long long& c,
                                     unsigned long long a,
                                     unsigned long long b) {
    asm("fma.rn.f32x2 %0, %1, %2, %0;" : "+l"(c) : "l"(a), "l"(b));
}

// ---------------- SGEMM: C[M,N] = A[M,K] @ B[K,N], row-major ----------------
// BM=BN=128, BK=16, 256 threads, 8x8 per-thread, f32x2 packed accumulation.
// Requires: M % 128 == 0, K % 16 == 0, N % 8 == 0 (N may be non-mult of 128).
__global__ __launch_bounds__(256, 2)
void sgemm_kernel(const float* __restrict__ A, const float* __restrict__ B,
                  float* __restrict__ C, int M, int N, int K)
{
    __shared__ float As[16][132];   // transposed A tile, pad 4 for bank spread
    __shared__ float Bs[16][128];

    const int tid = threadIdx.x;
    const int tx  = tid & 15;       // n-direction (8 cols each)
    const int ty  = tid >> 4;       // m-direction (8 rows each)
    const int m0  = blockIdx.y << 7;
    const int n0  = blockIdx.x << 7;

    const int a_row = tid >> 2;          // 0..63  (x2 iterations)
    const int a_col = (tid & 3) << 2;    // 0,4,8,12
    const int b_row = tid >> 5;          // 0..7   (x2 iterations)
    const int b_col = (tid & 31) << 2;   // 0..124

    unsigned long long c2[8][4];
    #pragma unroll
    for (int i = 0; i < 8; i++)
        #pragma unroll
        for (int j = 0; j < 4; j++) c2[i][j] = 0ULL;

    for (int k0 = 0; k0 < K; k0 += 16) {
        #pragma unroll
        for (int r = 0; r < 2; r++) {
            int row = a_row + 64 * r;
            float4 av = *(const float4*)(A + (size_t)(m0 + row) * K + (k0 + a_col));
            As[a_col + 0][row] = av.x;
            As[a_col + 1][row] = av.y;
            As[a_col + 2][row] = av.z;
            As[a_col + 3][row] = av.w;
        }
        #pragma unroll
        for (int r = 0; r < 2; r++) {
            int row = b_row + 8 * r;
            int col = n0 + b_col;
            float4 bv = make_float4(0.f, 0.f, 0.f, 0.f);
            if (col < N)
                bv = *(const float4*)(B + (size_t)(k0 + row) * N + col);
            *(float4*)(&Bs[row][b_col]) = bv;
        }
        __syncthreads();

        #pragma unroll
        for (int k = 0; k < 16; k++) {
            float a[8];
            *(float4*)(&a[0]) = *(const float4*)(&As[k][ty * 8]);
            *(float4*)(&a[4]) = *(const float4*)(&As[k][ty * 8 + 4]);
            unsigned long long b2[4];
            const unsigned long long* bp =
                (const unsigned long long*)(&Bs[k][tx * 8]);
            #pragma unroll
            for (int j = 0; j < 4; j++) b2[j] = bp[j];
            #pragma unroll
            for (int i = 0; i < 8; i++) {
                unsigned long long a2 = pack_dup(a[i]);
                #pragma unroll
                for (int j = 0; j < 4; j++) fma2(c2[i][j], a2, b2[j]);
            }
        }
        __syncthreads();
    }

    const int col = n0 + tx * 8;
    if (col < N) {
        #pragma unroll
        for (int i = 0; i < 8; i++) {
            int row = m0 + ty * 8 + i;
            float2 f0 = *(float2*)&c2[i][0];
            float2 f1 = *(float2*)&c2[i][1];
            float2 f2 = *(float2*)&c2[i][2];
            float2 f3 = *(float2*)&c2[i][3];
            *(float4*)(C + (size_t)row * N + col)     = make_float4(f0.x, f0.y, f1.x, f1.y);
            *(float4*)(C + (size_t)row * N + col + 4) = make_float4(f2.x, f2.y, f3.x, f3.y);
        }
    }
}

// ---------------- RMSNorm (block per row) ----------------
__global__ void rmsnorm_kernel(const float* __restrict__ in, float* __restrict__ out,
                               const float* __restrict__ w, int len,
                               int in_stride, int out_stride)
{
    const int row = blockIdx.x;
    const float* ip = in + (size_t)row * in_stride;
    float* op = out + (size_t)row * out_stride;

    float ss = 0.f;
    for (int i = threadIdx.x; i < len; i += blockDim.x) {
        float v = ip[i];
        ss += v * v;
    }
    __shared__ float red[256];
    red[threadIdx.x] = ss;
    __syncthreads();
    #pragma unroll
    for (int s = 128; s > 0; s >>= 1) {
        if (threadIdx.x < s) red[threadIdx.x] += red[threadIdx.x + s];
        __syncthreads();
    }
    const float r = rsqrtf(red[0] / (float)len + 1e-6f);
    for (int i = threadIdx.x; i < len; i += blockDim.x) {
        float v = ip[i] * r;
        if (w) v *= w[i];
        op[i] = v;
    }
}

// ---------------- RoPE on q ----------------
// Reference quirk: q_rope is RESHAPED (b,s,h,dr)->(b,h,s,dr), so the effective
// rope position for original (s,h) is ((s*16 + h) mod 4096) + start_pos.
__global__ void rope_q_kernel(float* __restrict__ q, const int* __restrict__ start_pos)
{
    int idx = blockIdx.x * blockDim.x + threadIdx.x;
    if (idx >= T_TOKENS * NH * 32) return;
    const int i = idx & 31;
    const int h = (idx >> 5) & 15;
    const int t = idx >> 9;
    const int s = t & (SEQ - 1);
    const int pos = ((s * NH + h) & (SEQ - 1)) + start_pos[0];

    const float theta = powf(10000.0f, -(float)i * (1.0f / 32.0f));
    const float ang = (float)pos * theta;
    float sn, cs;
    sincosf(ang, &sn, &cs);

    float* base = q + (size_t)t * QDIM + h * HD + DN;
    const float x1 = base[i];
    const float x2 = base[i + 32];
    base[i]      = x1 * cs - x2 * sn;
    base[i + 32] = x2 * cs + x1 * sn;
}

// ---------------- RoPE on k_pe ----------------
// Reference quirk: k_pe goes through rope() with shape (b,s,1,dr), so
// seq_len==1 and EVERY token uses position == start_pos.
__global__ void rope_k_kernel(float* __restrict__ kv, const int* __restrict__ start_pos)
{
    int idx = blockIdx.x * blockDim.x + threadIdx.x;
    if (idx >= T_TOKENS * 32) return;
    const int i = idx & 31;
    const int t = idx >> 5;
    const int pos = start_pos[0];

    const float theta = powf(10000.0f, -(float)i * (1.0f / 32.0f));
    const float ang = (float)pos * theta;
    float sn, cs;
    sincosf(ang, &sn, &cs);

    float* base = kv + (size_t)t * KVA + KVL;
    const float x1 = base[i];
    const float x2 = base[i + 32];
    base[i]      = x1 * cs - x2 * sn;
    base[i + 32] = x2 * cs + x1 * sn;
}

// ---------------- per-token attention over heads (16x16) ----------------
// scores[qh,kh] = (q[t,qh,:] . k[t,kh,:]) / sqrt(192);  k = [k_nope | k_pe]
// context[t,qh,:] = softmax(scores) @ v
__global__ __launch_bounds__(512)
void attn_kernel(const float* __restrict__ q, const float* __restrict__ kvup,
                 const float* __restrict__ kv, float* __restrict__ ctx)
{
    const int t = blockIdx.x;
    __shared__ float ks[16][HD];   // 16 x 192
    __shared__ float vs[16][DV];   // 16 x 128

    const float* ku = kvup + (size_t)t * KVUPD;
    const float* pe = kv + (size_t)t * KVA + KVL;

    for (int idx = threadIdx.x; idx < 16 * 256; idx += blockDim.x) {
        const int kh = idx >> 8;
        const int c  = idx & 255;
        const float v = ku[idx];
        if (c < DN) ks[kh][c] = v;
        else        vs[kh][c - DN] = v;
    }
    for (int idx = threadIdx.x; idx < 16 * DR; idx += blockDim.x) {
        const int kh = idx >> 6;
        const int c  = idx & 63;
        ks[kh][DN + c] = pe[c];
    }
    __syncthreads();

    const int w    = threadIdx.x >> 5;   // q head
    const int lane = threadIdx.x & 31;
    const float* qr = q + (size_t)t * QDIM + w * HD;

    float qreg[6];
    #pragma unroll
    for (int e = 0; e < 6; e++) qreg[e] = qr[lane + 32 * e];

    float sc[16];
    #pragma unroll
    for (int kh = 0; kh < 16; kh++) {
        float p = 0.f;
        #pragma unroll
        for (int e = 0; e < 6; e++) p += qreg[e] * ks[kh][lane + 32 * e];
        #pragma unroll
        for (int o = 16; o > 0; o >>= 1) p += __shfl_xor_sync(0xffffffffu, p, o);
        sc[kh] = p * 0.07216878364870323f;   // 1/sqrt(192)
    }

    float m = sc[0];
    #pragma unroll
    for (int kh = 1; kh < 16; kh++) m = fmaxf(m, sc[kh]);
    float sum = 0.f;
    #pragma unroll
    for (int kh = 0; kh < 16; kh++) { sc[kh] = expf(sc[kh] - m); sum += sc[kh]; }
    const float inv = 1.f / sum;

    float acc[4] = {0.f, 0.f, 0.f, 0.f};
    #pragma unroll
    for (int kh = 0; kh < 16; kh++) {
        const float p = sc[kh] * inv;
        #pragma unroll
        for (int j = 0; j < 4; j++) acc[j] += p * vs[kh][lane + 32 * j];
    }

    float* o = ctx + (size_t)t * (NH * DV) + w * DV;
    #pragma unroll
    for (int j = 0; j < 4; j++) o[lane + 32 * j] = acc[j];
}

// ---------------- launcher ----------------
extern "C" void kernel_launch(void* const* d_in, const int* in_sizes, int n_in,
                              void* d_out, int out_size)
{
    const float* x        = (const float*)d_in[0];
    const float* wq_a     = (const float*)d_in[1];
    const float* q_norm_w = (const float*)d_in[2];
    const float* wq_b     = (const float*)d_in[3];
    const float* wkv_a    = (const float*)d_in[4];
    const float* wkv_b    = (const float*)d_in[5];
    const float* wo       = (const float*)d_in[6];
    const int*   start_pos = (const int*)d_in[7];
    float* out = (float*)d_out;

    float *qa, *qb, *kvb, *kvn, *kvup, *ctx;
    cudaGetSymbolAddress((void**)&qa,   g_qa);
    cudaGetSymbolAddress((void**)&qb,   g_q);
    cudaGetSymbolAddress((void**)&kvb,  g_kv);
    cudaGetSymbolAddress((void**)&kvn,  g_kvn);
    cudaGetSymbolAddress((void**)&kvup, g_kvup);
    cudaGetSymbolAddress((void**)&ctx,  g_ctx);

    const int MT = T_TOKENS / 128;   // 128 m-tiles

    // 1) q_a = x @ wq_a            [16384,2048] x [2048,1536]
    sgemm_kernel<<<dim3(QLORA / 128, MT), 256>>>(x, wq_a, qa, T_TOKENS, QLORA, DIM);
    // 2) rmsnorm(q_a) * q_norm_w   (in place)
    rmsnorm_kernel<<<T_TOKENS, 256>>>(qa, qa, q_norm_w, QLORA, QLORA, QLORA);
    // 3) q = q_a @ wq_b            [16384,1536] x [1536,3072]
    sgemm_kernel<<<dim3(QDIM / 128, MT), 256>>>(qa, wq_b, qb, T_TOKENS, QDIM, QLORA);
    // 4) kv = x @ wkv_a            [16384,2048] x [2048,576]  (N=576 -> 5 n-tiles)
    sgemm_kernel<<<dim3((KVA + 127) / 128, MT), 256>>>(x, wkv_a, kvb, T_TOKENS, KVA, DIM);
    // 5) RoPE
    rope_q_kernel<<<(T_TOKENS * NH * 32 + 255) / 256, 256>>>(qb, start_pos);
    rope_k_kernel<<<(T_TOKENS * 32 + 255) / 256, 256>>>(kvb, start_pos);
    // 6) kv_c rmsnorm (weight = 1) -> kvn
    rmsnorm_kernel<<<T_TOKENS, 256>>>(kvb, kvn, nullptr, KVL, KVA, KVL);
    // 7) kv_up = kvn @ wkv_b       [16384,512] x [512,4096]
    sgemm_kernel<<<dim3(KVUPD / 128, MT), 256>>>(kvn, wkv_b, kvup, T_TOKENS, KVUPD, KVL);
    // 8) per-token 16x16 attention -> ctx
    attn_kernel<<<T_TOKENS, 512>>>(qb, kvup, kvb, ctx);
    // 9) out = ctx @ wo            [16384,2048] x [2048,2048]
    sgemm_kernel<<<dim3(DIM / 128, MT), 256>>>(ctx, wo, out, T_TOKENS, DIM, DIM);
}

// round 14
// speedup vs baseline: 2.0942x; 2.0938x over previous
#include <cuda_runtime.h>
#include <cuda_bf16.h>
#include <cstdint>

// ---------------- problem constants ----------------
#define T_TOKENS 16384      // b*s = 4*4096
#define SEQ      4096
#define DIM      2048
#define QLORA    1536
#define NH       16
#define DN       128
#define DR       64
#define DV       128
#define KVL      512
#define HD       192        // DN+DR
#define QDIM     3072       // NH*HD
#define KVA      576        // KVL+DR
#define KVUPD    4096       // NH*(DN+DV)

// ---------------- scratch (no allocs allowed) ----------------
__device__ float g_qa  [(size_t)T_TOKENS * QLORA];
__device__ float g_q   [(size_t)T_TOKENS * QDIM];
__device__ float g_kv  [(size_t)T_TOKENS * KVA];
__device__ float g_kvup[(size_t)T_TOKENS * KVUPD];

// bf16 split activations
__device__ __nv_bfloat16 g_xs_h [(size_t)T_TOKENS * DIM];
__device__ __nv_bfloat16 g_xs_l [(size_t)T_TOKENS * DIM];
__device__ __nv_bfloat16 g_qan_h[(size_t)T_TOKENS * QLORA];
__device__ __nv_bfloat16 g_qan_l[(size_t)T_TOKENS * QLORA];
__device__ __nv_bfloat16 g_kvn_h[(size_t)T_TOKENS * KVL];
__device__ __nv_bfloat16 g_kvn_l[(size_t)T_TOKENS * KVL];
__device__ __nv_bfloat16 g_ctx_h[(size_t)T_TOKENS * (NH * DV)];
__device__ __nv_bfloat16 g_ctx_l[(size_t)T_TOKENS * (NH * DV)];

// bf16 split weights, TRANSPOSED to [N][K]
__device__ __nv_bfloat16 g_wqa_h [(size_t)QLORA * DIM];
__device__ __nv_bfloat16 g_wqa_l [(size_t)QLORA * DIM];
__device__ __nv_bfloat16 g_wqb_h [(size_t)QDIM * QLORA];
__device__ __nv_bfloat16 g_wqb_l [(size_t)QDIM * QLORA];
__device__ __nv_bfloat16 g_wkva_h[(size_t)KVA * DIM];
__device__ __nv_bfloat16 g_wkva_l[(size_t)KVA * DIM];
__device__ __nv_bfloat16 g_wkvb_h[(size_t)KVUPD * KVL];
__device__ __nv_bfloat16 g_wkvb_l[(size_t)KVUPD * KVL];
__device__ __nv_bfloat16 g_wo_h  [(size_t)DIM * DIM];
__device__ __nv_bfloat16 g_wo_l  [(size_t)DIM * DIM];

// ---------------- PTX helpers (sm_80-compatible only) ----------------
__device__ __forceinline__ uint32_t smem_u32(const void* p) {
    uint32_t a;
    asm("{ .reg .u64 t; cvta.to.shared.u64 t, %1; cvt.u32.u64 %0, t; }"
        : "=r"(a) : "l"(p));
    return a;
}
__device__ __forceinline__ void cpa16(uint32_t dst, const void* src, int sz) {
    asm volatile("cp.async.cg.shared.global [%0], [%1], 16, %2;"
                 :: "r"(dst), "l"(src), "r"(sz));
}
__device__ __forceinline__ void ldm4(uint32_t* r, uint32_t a) {
    asm volatile("ldmatrix.sync.aligned.m8n8.x4.shared.b16 {%0,%1,%2,%3}, [%4];"
                 : "=r"(r[0]), "=r"(r[1]), "=r"(r[2]), "=r"(r[3]) : "r"(a));
}
__device__ __forceinline__ void mma16816(float* d, const uint32_t* a, const uint32_t* b) {
    asm volatile(
        "mma.sync.aligned.m16n8k16.row.col.f32.bf16.bf16.f32 "
        "{%0,%1,%2,%3}, {%4,%5,%6,%7}, {%8,%9}, {%0,%1,%2,%3};"
        : "+f"(d[0]), "+f"(d[1]), "+f"(d[2]), "+f"(d[3])
        : "r"(a[0]), "r"(a[1]), "r"(a[2]), "r"(a[3]), "r"(b[0]), "r"(b[1]));
}

// ---------------- HMMA GEMM ----------------
// C[M,N] fp32 = (Ah+Al)[M,K] @ (Bh+Bl)^T,  B arrays stored [N][K] bf16.
// 3-term compensated: Ah@Bh + Ah@Bl + Al@Bh, fp32 accumulators.
// CTA tile 128x128, BK=32, 8 warps (warp tile 64x32), 3-stage cp.async pipeline.
#define BM 128
#define BN 128
#define BK 32
#define ROWB 80                       // bytes per smem row (32 halfs + 8 pad)
#define MAT_BYTES (128 * ROWB)        // 10240 per matrix tile
#define STAGE_BYTES (4 * MAT_BYTES)   // Ah|Al|Bh|Bl = 40960
#define STAGES 3
#define DYN_SMEM (STAGES * STAGE_BYTES)   // 122880

__device__ __forceinline__ void stage_chunk(
    uint32_t sbase,
    const __nv_bfloat16* __restrict__ Ah, const __nv_bfloat16* __restrict__ Al,
    const __nv_bfloat16* __restrict__ Bh, const __nv_bfloat16* __restrict__ Bl,
    int m0, int n0, int N, int K, int k0, int tid)
{
    #pragma unroll
    for (int i = 0; i < 2; i++) {
        const int idx = tid + 256 * i;
        const int row = idx >> 2;
        const int kc  = idx & 3;
        const uint32_t off = (uint32_t)(row * ROWB + kc * 16);
        const size_t ga = (size_t)(m0 + row) * K + k0 + kc * 8;
        cpa16(sbase + off,              Ah + ga, 16);
        cpa16(sbase + MAT_BYTES + off,  Al + ga, 16);
        const int n = n0 + row;
        const int sz = (n < N) ? 16 : 0;
        const size_t gb = (size_t)(n < N ? n : 0) * K + k0 + kc * 8;
        cpa16(sbase + 2 * MAT_BYTES + off, Bh + gb, sz);
        cpa16(sbase + 3 * MAT_BYTES + off, Bl + gb, sz);
    }
    asm volatile("cp.async.commit_group;");
}

__global__ __launch_bounds__(256, 1)
void sgemm_mma(const __nv_bfloat16* __restrict__ Ah, const __nv_bfloat16* __restrict__ Al,
               const __nv_bfloat16* __restrict__ Bh, const __nv_bfloat16* __restrict__ Bl,
               float* __restrict__ C, int M, int N, int K)
{
    extern __shared__ char dynsm[];
    const uint32_t sb = smem_u32(dynsm);

    const int tid  = threadIdx.x;
    const int wid  = tid >> 5;
    const int lane = tid & 31;
    const int m0 = blockIdx.y * BM;
    const int n0 = blockIdx.x * BN;

    const int warp_m = (wid >> 2) * 64;   // 0 or 64
    const int warp_n = (wid & 3) * 32;    // 0,32,64,96

    float acc[4][4][4];
    #pragma unroll
    for (int i = 0; i < 4; i++)
        #pragma unroll
        for (int j = 0; j < 4; j++)
            #pragma unroll
            for (int r = 0; r < 4; r++) acc[i][j][r] = 0.f;

    const int NC = K / BK;

    // prologue: stage chunks 0, 1
    stage_chunk(sb, Ah, Al, Bh, Bl, m0, n0, N, K, 0, tid);
    stage_chunk(sb + STAGE_BYTES, Ah, Al, Bh, Bl, m0, n0, N, K, BK, tid);

    // precomputed ldmatrix lane offsets
    const int a_row = ((lane >> 3) & 1) * 8 + (lane & 7);
    const int a_colb = (lane >> 4) * 16;          // bytes
    const int b_row = ((lane >> 4) & 1) * 8 + (lane & 7);
    const int b_colb = ((lane >> 3) & 1) * 16;    // bytes

    for (int c = 0; c < NC; ++c) {
        if (c < NC - 1) asm volatile("cp.async.wait_group 1;");
        else            asm volatile("cp.async.wait_group 0;");
        __syncthreads();

        if (c + 2 < NC)
            stage_chunk(sb + ((c + 2) % STAGES) * STAGE_BYTES,
                        Ah, Al, Bh, Bl, m0, n0, N, K, (c + 2) * BK, tid);

        const uint32_t st = sb + (c % STAGES) * STAGE_BYTES;

        #pragma unroll
        for (int ks = 0; ks < 2; ks++) {
            const int kkb = ks * 32;   // k offset in bytes (16 halfs)

            uint32_t fa_h[4][4], fa_l[4][4];
            #pragma unroll
            for (int i = 0; i < 4; i++) {
                const uint32_t ad = st + (uint32_t)((warp_m + 16 * i + a_row) * ROWB
                                                    + kkb + a_colb);
                ldm4(fa_h[i], ad);
                ldm4(fa_l[i], ad + MAT_BYTES);
            }
            uint32_t fb_h[4][2], fb_l[4][2];
            #pragma unroll
            for (int jj = 0; jj < 2; jj++) {
                const uint32_t bd = st + 2 * MAT_BYTES
                    + (uint32_t)((warp_n + 16 * jj + b_row) * ROWB + kkb + b_colb);
                uint32_t r[4];
                ldm4(r, bd);
                fb_h[2*jj][0] = r[0]; fb_h[2*jj][1] = r[1];
                fb_h[2*jj+1][0] = r[2]; fb_h[2*jj+1][1] = r[3];
                ldm4(r, bd + MAT_BYTES);
                fb_l[2*jj][0] = r[0]; fb_l[2*jj][1] = r[1];
                fb_l[2*jj+1][0] = r[2]; fb_l[2*jj+1][1] = r[3];
            }
            #pragma unroll
            for (int i = 0; i < 4; i++)
                #pragma unroll
                for (int j = 0; j < 4; j++) {
                    mma16816(acc[i][j], fa_h[i], fb_h[j]);
                    mma16816(acc[i][j], fa_h[i], fb_l[j]);
                    mma16816(acc[i][j], fa_l[i], fb_h[j]);
                }
        }
        __syncthreads();
    }

    // epilogue: fragment (i,j): d0,d1 -> (row, col..col+1); d2,d3 -> (row+8, ..)
    const int er = lane >> 2;
    const int ec = (lane & 3) * 2;
    #pragma unroll
    for (int i = 0; i < 4; i++) {
        const int row = m0 + warp_m + 16 * i + er;
        #pragma unroll
        for (int j = 0; j < 4; j++) {
            const int col = n0 + warp_n + 8 * j + ec;
            if (col < N) {
                float* cp0 = C + (size_t)row * N + col;
                *(float2*)cp0 = make_float2(acc[i][j][0], acc[i][j][1]);
                *(float2*)(cp0 + 8 * (size_t)N) = make_float2(acc[i][j][2], acc[i][j][3]);
            }
        }
    }
}

// ---------------- weight transpose + bf16 split ----------------
__global__ void wsplit_T(const float* __restrict__ W, __nv_bfloat16* __restrict__ Th,
                         __nv_bfloat16* __restrict__ Tl, int R, int Cc)
{
    __shared__ float t[32][33];
    const int c0 = blockIdx.x * 32, r0 = blockIdx.y * 32;
    const int tx = threadIdx.x, ty = threadIdx.y;   // 32 x 8
    #pragma unroll
    for (int i = 0; i < 32; i += 8)
        t[ty + i][tx] = W[(size_t)(r0 + ty + i) * Cc + c0 + tx];
    __syncthreads();
    #pragma unroll
    for (int i = 0; i < 32; i += 8) {
        float v = t[tx][ty + i];
        __nv_bfloat16 h = __float2bfloat16(v);
        __nv_bfloat16 l = __float2bfloat16(v - __bfloat162float(h));
        size_t o = (size_t)(c0 + ty + i) * R + r0 + tx;
        Th[o] = h; Tl[o] = l;
    }
}

// ---------------- activation bf16 split ----------------
__global__ void asplit(const float* __restrict__ src, __nv_bfloat16* __restrict__ h,
                       __nv_bfloat16* __restrict__ l, int n4)
{
    int i = blockIdx.x * blockDim.x + threadIdx.x;
    if (i >= n4) return;
    float4 v = ((const float4*)src)[i];
    __nv_bfloat16 h0 = __float2bfloat16(v.x), h1 = __float2bfloat16(v.y);
    __nv_bfloat16 h2 = __float2bfloat16(v.z), h3 = __float2bfloat16(v.w);
    ((__nv_bfloat162*)h)[2*i]   = __nv_bfloat162(h0, h1);
    ((__nv_bfloat162*)h)[2*i+1] = __nv_bfloat162(h2, h3);
    ((__nv_bfloat162*)l)[2*i]   = __nv_bfloat162(
        __float2bfloat16(v.x - __bfloat162float(h0)),
        __float2bfloat16(v.y - __bfloat162float(h1)));
    ((__nv_bfloat162*)l)[2*i+1] = __nv_bfloat162(
        __float2bfloat16(v.z - __bfloat162float(h2)),
        __float2bfloat16(v.w - __bfloat162float(h3)));
}

// ---------------- RMSNorm + bf16 split ----------------
__global__ void rmsnorm_split(const float* __restrict__ in, __nv_bfloat16* __restrict__ oh,
                              __nv_bfloat16* __restrict__ ol, const float* __restrict__ w,
                              int len, int in_stride)
{
    const int row = blockIdx.x;
    const float* ip = in + (size_t)row * in_stride;
    float ss = 0.f;
    for (int i = threadIdx.x; i < len; i += blockDim.x) {
        float v = ip[i];
        ss += v * v;
    }
    __shared__ float red[256];
    red[threadIdx.x] = ss;
    __syncthreads();
    #pragma unroll
    for (int s = 128; s > 0; s >>= 1) {
        if (threadIdx.x < s) red[threadIdx.x] += red[threadIdx.x + s];
        __syncthreads();
    }
    const float r = rsqrtf(red[0] / (float)len + 1e-6f);
    for (int i = threadIdx.x; i < len; i += blockDim.x) {
        float v = ip[i] * r;
        if (w) v *= w[i];
        __nv_bfloat16 h = __float2bfloat16(v);
        size_t o = (size_t)row * len + i;
        oh[o] = h;
        ol[o] = __float2bfloat16(v - __bfloat162float(h));
    }
}

// ---------------- RoPE on q (reshape quirk preserved) ----------------
__global__ void rope_q_kernel(float* __restrict__ q, const int* __restrict__ start_pos)
{
    int idx = blockIdx.x * blockDim.x + threadIdx.x;
    if (idx >= T_TOKENS * NH * 32) return;
    const int i = idx & 31;
    const int h = (idx >> 5) & 15;
    const int t = idx >> 9;
    const int s = t & (SEQ - 1);
    const int pos = ((s * NH + h) & (SEQ - 1)) + start_pos[0];

    const float theta = powf(10000.0f, -(float)i * (1.0f / 32.0f));
    const float ang = (float)pos * theta;
    float sn, cs;
    sincosf(ang, &sn, &cs);

    float* base = q + (size_t)t * QDIM + h * HD + DN;
    const float x1 = base[i];
    const float x2 = base[i + 32];
    base[i]      = x1 * cs - x2 * sn;
    base[i + 32] = x2 * cs + x1 * sn;
}

// ---------------- RoPE on k_pe (seq_len==1 quirk: pos = start_pos) ----------------
__global__ void rope_k_kernel(float* __restrict__ kv, const int* __restrict__ start_pos)
{
    int idx = blockIdx.x * blockDim.x + threadIdx.x;
    if (idx >= T_TOKENS * 32) return;
    const int i = idx & 31;
    const int t = idx >> 5;
    const int pos = start_pos[0];

    const float theta = powf(10000.0f, -(float)i * (1.0f / 32.0f));
    const float ang = (float)pos * theta;
    float sn, cs;
    sincosf(ang, &sn, &cs);

    float* base = kv + (size_t)t * KVA + KVL;
    const float x1 = base[i];
    const float x2 = base[i + 32];
    base[i]      = x1 * cs - x2 * sn;
    base[i + 32] = x2 * cs + x1 * sn;
}

// ---------------- per-token 16x16 attention, fused ctx bf16 split ----------------
__global__ __launch_bounds__(512)
void attn_kernel(const float* __restrict__ q, const float* __restrict__ kvup,
                 const float* __restrict__ kv,
                 __nv_bfloat16* __restrict__ ctx_h, __nv_bfloat16* __restrict__ ctx_l)
{
    const int t = blockIdx.x;
    __shared__ float ks[16][HD];
    __shared__ float vs[16][DV];

    const float* ku = kvup + (size_t)t * KVUPD;
    const float* pe = kv + (size_t)t * KVA + KVL;

    for (int idx = threadIdx.x; idx < 16 * 256; idx += blockDim.x) {
        const int kh = idx >> 8;
        const int c  = idx & 255;
        const float v = ku[idx];
        if (c < DN) ks[kh][c] = v;
        else        vs[kh][c - DN] = v;
    }
    for (int idx = threadIdx.x; idx < 16 * DR; idx += blockDim.x) {
        const int kh = idx >> 6;
        const int c  = idx & 63;
        ks[kh][DN + c] = pe[c];
    }
    __syncthreads();

    const int w    = threadIdx.x >> 5;
    const int lane = threadIdx.x & 31;
    const float* qr = q + (size_t)t * QDIM + w * HD;

    float qreg[6];
    #pragma unroll
    for (int e = 0; e < 6; e++) qreg[e] = qr[lane + 32 * e];

    float sc[16];
    #pragma unroll
    for (int kh = 0; kh < 16; kh++) {
        float p = 0.f;
        #pragma unroll
        for (int e = 0; e < 6; e++) p += qreg[e] * ks[kh][lane + 32 * e];
        #pragma unroll
        for (int o = 16; o > 0; o >>= 1) p += __shfl_xor_sync(0xffffffffu, p, o);
        sc[kh] = p * 0.07216878364870323f;   // 1/sqrt(192)
    }

    float m = sc[0];
    #pragma unroll
    for (int kh = 1; kh < 16; kh++) m = fmaxf(m, sc[kh]);
    float sum = 0.f;
    #pragma unroll
    for (int kh = 0; kh < 16; kh++) { sc[kh] = expf(sc[kh] - m); sum += sc[kh]; }
    const float inv = 1.f / sum;

    float acc[4] = {0.f, 0.f, 0.f, 0.f};
    #pragma unroll
    for (int kh = 0; kh < 16; kh++) {
        const float p = sc[kh] * inv;
        #pragma unroll
        for (int j = 0; j < 4; j++) acc[j] += p * vs[kh][lane + 32 * j];
    }

    const size_t ob = (size_t)t * (NH * DV) + w * DV;
    #pragma unroll
    for (int j = 0; j < 4; j++) {
        float v = acc[j];
        __nv_bfloat16 h = __float2bfloat16(v);
        ctx_h[ob + lane + 32 * j] = h;
        ctx_l[ob + lane + 32 * j] = __float2bfloat16(v - __bfloat162float(h));
    }
}

// ---------------- launcher ----------------
extern "C" void kernel_launch(void* const* d_in, const int* in_sizes, int n_in,
                              void* d_out, int out_size)
{
    const float* x        = (const float*)d_in[0];
    const float* wq_a     = (const float*)d_in[1];
    const float* q_norm_w = (const float*)d_in[2];
    const float* wq_b     = (const float*)d_in[3];
    const float* wkv_a    = (const float*)d_in[4];
    const float* wkv_b    = (const float*)d_in[5];
    const float* wo       = (const float*)d_in[6];
    const int*   start_pos = (const int*)d_in[7];
    float* out = (float*)d_out;

    float *qa, *qb, *kvb, *kvup;
    cudaGetSymbolAddress((void**)&qa,   g_qa);
    cudaGetSymbolAddress((void**)&qb,   g_q);
    cudaGetSymbolAddress((void**)&kvb,  g_kv);
    cudaGetSymbolAddress((void**)&kvup, g_kvup);

    __nv_bfloat16 *xs_h, *xs_l, *qan_h, *qan_l, *kvn_h, *kvn_l, *ctx_h, *ctx_l;
    cudaGetSymbolAddress((void**)&xs_h,  g_xs_h);  cudaGetSymbolAddress((void**)&xs_l,  g_xs_l);
    cudaGetSymbolAddress((void**)&qan_h, g_qan_h); cudaGetSymbolAddress((void**)&qan_l, g_qan_l);
    cudaGetSymbolAddress((void**)&kvn_h, g_kvn_h); cudaGetSymbolAddress((void**)&kvn_l, g_kvn_l);
    cudaGetSymbolAddress((void**)&ctx_h, g_ctx_h); cudaGetSymbolAddress((void**)&ctx_l, g_ctx_l);

    __nv_bfloat16 *wqa_h, *wqa_l, *wqb_h, *wqb_l, *wkva_h, *wkva_l, *wkvb_h, *wkvb_l, *wo_h, *wo_l;
    cudaGetSymbolAddress((void**)&wqa_h,  g_wqa_h);  cudaGetSymbolAddress((void**)&wqa_l,  g_wqa_l);
    cudaGetSymbolAddress((void**)&wqb_h,  g_wqb_h);  cudaGetSymbolAddress((void**)&wqb_l,  g_wqb_l);
    cudaGetSymbolAddress((void**)&wkva_h, g_wkva_h); cudaGetSymbolAddress((void**)&wkva_l, g_wkva_l);
    cudaGetSymbolAddress((void**)&wkvb_h, g_wkvb_h); cudaGetSymbolAddress((void**)&wkvb_l, g_wkvb_l);
    cudaGetSymbolAddress((void**)&wo_h,   g_wo_h);   cudaGetSymbolAddress((void**)&wo_l,   g_wo_l);

    cudaFuncSetAttribute(sgemm_mma, cudaFuncAttributeMaxDynamicSharedMemorySize, DYN_SMEM);

    const dim3 wsblk(32, 8);
    const int M = T_TOKENS;

    // weight transpose-splits (W[R][C] -> T[C][R])
    wsplit_T<<<dim3(QLORA/32, DIM/32),  wsblk>>>(wq_a,  wqa_h,  wqa_l,  DIM,   QLORA);
    wsplit_T<<<dim3(QDIM/32,  QLORA/32),wsblk>>>(wq_b,  wqb_h,  wqb_l,  QLORA, QDIM);
    wsplit_T<<<dim3(KVA/32,   DIM/32),  wsblk>>>(wkv_a, wkva_h, wkva_l, DIM,   KVA);
    wsplit_T<<<dim3(KVUPD/32, KVL/32),  wsblk>>>(wkv_b, wkvb_h, wkvb_l, KVL,   KVUPD);
    wsplit_T<<<dim3(DIM/32,   DIM/32),  wsblk>>>(wo,    wo_h,   wo_l,   DIM,   DIM);

    // x split
    {
        int n4 = (T_TOKENS * DIM) / 4;
        asplit<<<(n4 + 255) / 256, 256>>>(x, xs_h, xs_l, n4);
    }

    // 1) qa = x @ wq_a   [16384,2048]x[2048,1536]
    sgemm_mma<<<dim3(QLORA/BN, M/BM), 256, DYN_SMEM>>>(
        xs_h, xs_l, wqa_h, wqa_l, qa, M, QLORA, DIM);
    // 2) rmsnorm + split
    rmsnorm_split<<<T_TOKENS, 256>>>(qa, qan_h, qan_l, q_norm_w, QLORA, QLORA);
    // 3) q = qan @ wq_b  [16384,1536]x[1536,3072]
    sgemm_mma<<<dim3(QDIM/BN, M/BM), 256, DYN_SMEM>>>(
        qan_h, qan_l, wqb_h, wqb_l, qb, M, QDIM, QLORA);
    // 4) kv = x @ wkv_a  [16384,2048]x[2048,576]
    sgemm_mma<<<dim3((KVA + BN - 1)/BN, M/BM), 256, DYN_SMEM>>>(
        xs_h, xs_l, wkva_h, wkva_l, kvb, M, KVA, DIM);
    // 5) RoPE
    rope_q_kernel<<<(T_TOKENS * NH * 32 + 255) / 256, 256>>>(qb, start_pos);
    rope_k_kernel<<<(T_TOKENS * 32 + 255) / 256, 256>>>(kvb, start_pos);
    // 6) kv_c rmsnorm (weight = 1) + split
    rmsnorm_split<<<T_TOKENS, 256>>>(kvb, kvn_h, kvn_l, nullptr, KVL, KVA);
    // 7) kv_up = kvn @ wkv_b  [16384,512]x[512,4096]
    sgemm_mma<<<dim3(KVUPD/BN, M/BM), 256, DYN_SMEM>>>(
        kvn_h, kvn_l, wkvb_h, wkvb_l, kvup, M, KVUPD, KVL);
    // 8) per-token attention -> ctx (split)
    attn_kernel<<<T_TOKENS, 512>>>(qb, kvup, kvb, ctx_h, ctx_l);
    // 9) out = ctx @ wo  [16384,2048]x[2048,2048]
    sgemm_mma<<<dim3(DIM/BN, M/BM), 256, DYN_SMEM>>>(
        ctx_h, ctx_l, wo_h, wo_l, out, M, DIM, DIM);
}

// round 15
// speedup vs baseline: 2.0942x; 1.0000x over previous
#include <cuda_runtime.h>
#include <cuda_bf16.h>
#include <cstdint>

// ---------------- problem constants ----------------
#define T_TOKENS 16384      // b*s = 4*4096
#define SEQ      4096
#define DIM      2048
#define QLORA    1536
#define NH       16
#define DN       128
#define DR       64
#define DV       128
#define KVL      512
#define HD       192        // DN+DR
#define QDIM     3072       // NH*HD
#define KVA      576        // KVL+DR
#define KVUPD    4096       // NH*(DN+DV)

// ---------------- scratch (no allocs allowed) ----------------
__device__ float g_qa  [(size_t)T_TOKENS * QLORA];
__device__ float g_q   [(size_t)T_TOKENS * QDIM];
__device__ float g_kv  [(size_t)T_TOKENS * KVA];
__device__ float g_kvup[(size_t)T_TOKENS * KVUPD];

// bf16 split activations
__device__ __nv_bfloat16 g_xs_h [(size_t)T_TOKENS * DIM];
__device__ __nv_bfloat16 g_xs_l [(size_t)T_TOKENS * DIM];
__device__ __nv_bfloat16 g_qan_h[(size_t)T_TOKENS * QLORA];
__device__ __nv_bfloat16 g_qan_l[(size_t)T_TOKENS * QLORA];
__device__ __nv_bfloat16 g_kvn_h[(size_t)T_TOKENS * KVL];
__device__ __nv_bfloat16 g_kvn_l[(size_t)T_TOKENS * KVL];
__device__ __nv_bfloat16 g_ctx_h[(size_t)T_TOKENS * (NH * DV)];
__device__ __nv_bfloat16 g_ctx_l[(size_t)T_TOKENS * (NH * DV)];

// bf16 split weights, TRANSPOSED to [N][K]
__device__ __nv_bfloat16 g_wqa_h [(size_t)QLORA * DIM];
__device__ __nv_bfloat16 g_wqa_l [(size_t)QLORA * DIM];
__device__ __nv_bfloat16 g_wqb_h [(size_t)QDIM * QLORA];
__device__ __nv_bfloat16 g_wqb_l [(size_t)QDIM * QLORA];
__device__ __nv_bfloat16 g_wkva_h[(size_t)KVA * DIM];
__device__ __nv_bfloat16 g_wkva_l[(size_t)KVA * DIM];
__device__ __nv_bfloat16 g_wkvb_h[(size_t)KVUPD * KVL];
__device__ __nv_bfloat16 g_wkvb_l[(size_t)KVUPD * KVL];
__device__ __nv_bfloat16 g_wo_h  [(size_t)DIM * DIM];
__device__ __nv_bfloat16 g_wo_l  [(size_t)DIM * DIM];

// ---------------- PTX helpers (sm_80-compatible only) ----------------
__device__ __forceinline__ uint32_t smem_u32(const void* p) {
    uint32_t a;
    asm("{ .reg .u64 t; cvta.to.shared.u64 t, %1; cvt.u32.u64 %0, t; }"
        : "=r"(a) : "l"(p));
    return a;
}
__device__ __forceinline__ void cpa16(uint32_t dst, const void* src, int sz) {
    asm volatile("cp.async.cg.shared.global [%0], [%1], 16, %2;"
                 :: "r"(dst), "l"(src), "r"(sz));
}
__device__ __forceinline__ void ldm4(uint32_t* r, uint32_t a) {
    asm volatile("ldmatrix.sync.aligned.m8n8.x4.shared.b16 {%0,%1,%2,%3}, [%4];"
                 : "=r"(r[0]), "=r"(r[1]), "=r"(r[2]), "=r"(r[3]) : "r"(a));
}
__device__ __forceinline__ void mma16816(float* d, const uint32_t* a, const uint32_t* b) {
    asm volatile(
        "mma.sync.aligned.m16n8k16.row.col.f32.bf16.bf16.f32 "
        "{%0,%1,%2,%3}, {%4,%5,%6,%7}, {%8,%9}, {%0,%1,%2,%3};"
        : "+f"(d[0]), "+f"(d[1]), "+f"(d[2]), "+f"(d[3])
        : "r"(a[0]), "r"(a[1]), "r"(a[2]), "r"(a[3]), "r"(b[0]), "r"(b[1]));
}

// ---------------- HMMA GEMM ----------------
// C[M,N] fp32 = (Ah+Al)[M,K] @ (Bh+Bl)^T,  B arrays stored [N][K] bf16.
// 3-term compensated: Ah@Bh + Ah@Bl + Al@Bh, fp32 accumulators.
// CTA tile 128x128, BK=32, 8 warps (warp tile 64x32), 3-stage cp.async pipeline.
#define BM 128
#define BN 128
#define BK 32
#define ROWB 80                       // bytes per smem row (32 halfs + 8 pad)
#define MAT_BYTES (128 * ROWB)        // 10240 per matrix tile
#define STAGE_BYTES (4 * MAT_BYTES)   // Ah|Al|Bh|Bl = 40960
#define STAGES 3
#define DYN_SMEM (STAGES * STAGE_BYTES)   // 122880

__device__ __forceinline__ void stage_chunk(
    uint32_t sbase,
    const __nv_bfloat16* __restrict__ Ah, const __nv_bfloat16* __restrict__ Al,
    const __nv_bfloat16* __restrict__ Bh, const __nv_bfloat16* __restrict__ Bl,
    int m0, int n0, int N, int K, int k0, int tid)
{
    #pragma unroll
    for (int i = 0; i < 2; i++) {
        const int idx = tid + 256 * i;
        const int row = idx >> 2;
        const int kc  = idx & 3;
        const uint32_t off = (uint32_t)(row * ROWB + kc * 16);
        const size_t ga = (size_t)(m0 + row) * K + k0 + kc * 8;
        cpa16(sbase + off,              Ah + ga, 16);
        cpa16(sbase + MAT_BYTES + off,  Al + ga, 16);
        const int n = n0 + row;
        const int sz = (n < N) ? 16 : 0;
        const size_t gb = (size_t)(n < N ? n : 0) * K + k0 + kc * 8;
        cpa16(sbase + 2 * MAT_BYTES + off, Bh + gb, sz);
        cpa16(sbase + 3 * MAT_BYTES + off, Bl + gb, sz);
    }
    asm volatile("cp.async.commit_group;");
}

__global__ __launch_bounds__(256, 1)
void sgemm_mma(const __nv_bfloat16* __restrict__ Ah, const __nv_bfloat16* __restrict__ Al,
               const __nv_bfloat16* __restrict__ Bh, const __nv_bfloat16* __restrict__ Bl,
               float* __restrict__ C, int M, int N, int K)
{
    extern __shared__ char dynsm[];
    const uint32_t sb = smem_u32(dynsm);

    const int tid  = threadIdx.x;
    const int wid  = tid >> 5;
    const int lane = tid & 31;
    const int m0 = blockIdx.y * BM;
    const int n0 = blockIdx.x * BN;

    const int warp_m = (wid >> 2) * 64;   // 0 or 64
    const int warp_n = (wid & 3) * 32;    // 0,32,64,96

    float acc[4][4][4];
    #pragma unroll
    for (int i = 0; i < 4; i++)
        #pragma unroll
        for (int j = 0; j < 4; j++)
            #pragma unroll
            for (int r = 0; r < 4; r++) acc[i][j][r] = 0.f;

    const int NC = K / BK;

    // prologue: stage chunks 0, 1
    stage_chunk(sb, Ah, Al, Bh, Bl, m0, n0, N, K, 0, tid);
    stage_chunk(sb + STAGE_BYTES, Ah, Al, Bh, Bl, m0, n0, N, K, BK, tid);

    // precomputed ldmatrix lane offsets
    const int a_row = ((lane >> 3) & 1) * 8 + (lane & 7);
    const int a_colb = (lane >> 4) * 16;          // bytes
    const int b_row = ((lane >> 4) & 1) * 8 + (lane & 7);
    const int b_colb = ((lane >> 3) & 1) * 16;    // bytes

    for (int c = 0; c < NC; ++c) {
        if (c < NC - 1) asm volatile("cp.async.wait_group 1;");
        else            asm volatile("cp.async.wait_group 0;");
        __syncthreads();

        if (c + 2 < NC)
            stage_chunk(sb + ((c + 2) % STAGES) * STAGE_BYTES,
                        Ah, Al, Bh, Bl, m0, n0, N, K, (c + 2) * BK, tid);

        const uint32_t st = sb + (c % STAGES) * STAGE_BYTES;

        #pragma unroll
        for (int ks = 0; ks < 2; ks++) {
            const int kkb = ks * 32;   // k offset in bytes (16 halfs)

            uint32_t fa_h[4][4], fa_l[4][4];
            #pragma unroll
            for (int i = 0; i < 4; i++) {
                const uint32_t ad = st + (uint32_t)((warp_m + 16 * i + a_row) * ROWB
                                                    + kkb + a_colb);
                ldm4(fa_h[i], ad);
                ldm4(fa_l[i], ad + MAT_BYTES);
            }
            uint32_t fb_h[4][2], fb_l[4][2];
            #pragma unroll
            for (int jj = 0; jj < 2; jj++) {
                const uint32_t bd = st + 2 * MAT_BYTES
                    + (uint32_t)((warp_n + 16 * jj + b_row) * ROWB + kkb + b_colb);
                uint32_t r[4];
                ldm4(r, bd);
                fb_h[2*jj][0] = r[0]; fb_h[2*jj][1] = r[1];
                fb_h[2*jj+1][0] = r[2]; fb_h[2*jj+1][1] = r[3];
                ldm4(r, bd + MAT_BYTES);
                fb_l[2*jj][0] = r[0]; fb_l[2*jj][1] = r[1];
                fb_l[2*jj+1][0] = r[2]; fb_l[2*jj+1][1] = r[3];
            }
            #pragma unroll
            for (int i = 0; i < 4; i++)
                #pragma unroll
                for (int j = 0; j < 4; j++) {
                    mma16816(acc[i][j], fa_h[i], fb_h[j]);
                    mma16816(acc[i][j], fa_h[i], fb_l[j]);
                    mma16816(acc[i][j], fa_l[i], fb_h[j]);
                }
        }
        __syncthreads();
    }

    // epilogue: fragment (i,j): d0,d1 -> (row, col..col+1); d2,d3 -> (row+8, ..)
    const int er = lane >> 2;
    const int ec = (lane & 3) * 2;
    #pragma unroll
    for (int i = 0; i < 4; i++) {
        const int row = m0 + warp_m + 16 * i + er;
        #pragma unroll
        for (int j = 0; j < 4; j++) {
            const int col = n0 + warp_n + 8 * j + ec;
            if (col < N) {
                float* cp0 = C + (size_t)row * N + col;
                *(float2*)cp0 = make_float2(acc[i][j][0], acc[i][j][1]);
                *(float2*)(cp0 + 8 * (size_t)N) = make_float2(acc[i][j][2], acc[i][j][3]);
            }
        }
    }
}

// ---------------- weight transpose + bf16 split ----------------
__global__ void wsplit_T(const float* __restrict__ W, __nv_bfloat16* __restrict__ Th,
                         __nv_bfloat16* __restrict__ Tl, int R, int Cc)
{
    __shared__ float t[32][33];
    const int c0 = blockIdx.x * 32, r0 = blockIdx.y * 32;
    const int tx = threadIdx.x, ty = threadIdx.y;   // 32 x 8
    #pragma unroll
    for (int i = 0; i < 32; i += 8)
        t[ty + i][tx] = W[(size_t)(r0 + ty + i) * Cc + c0 + tx];
    __syncthreads();
    #pragma unroll
    for (int i = 0; i < 32; i += 8) {
        float v = t[tx][ty + i];
        __nv_bfloat16 h = __float2bfloat16(v);
        __nv_bfloat16 l = __float2bfloat16(v - __bfloat162float(h));
        size_t o = (size_t)(c0 + ty + i) * R + r0 + tx;
        Th[o] = h; Tl[o] = l;
    }
}

// ---------------- activation bf16 split ----------------
__global__ void asplit(const float* __restrict__ src, __nv_bfloat16* __restrict__ h,
                       __nv_bfloat16* __restrict__ l, int n4)
{
    int i = blockIdx.x * blockDim.x + threadIdx.x;
    if (i >= n4) return;
    float4 v = ((const float4*)src)[i];
    __nv_bfloat16 h0 = __float2bfloat16(v.x), h1 = __float2bfloat16(v.y);
    __nv_bfloat16 h2 = __float2bfloat16(v.z), h3 = __float2bfloat16(v.w);
    ((__nv_bfloat162*)h)[2*i]   = __nv_bfloat162(h0, h1);
    ((__nv_bfloat162*)h)[2*i+1] = __nv_bfloat162(h2, h3);
    ((__nv_bfloat162*)l)[2*i]   = __nv_bfloat162(
        __float2bfloat16(v.x - __bfloat162float(h0)),
        __float2bfloat16(v.y - __bfloat162float(h1)));
    ((__nv_bfloat162*)l)[2*i+1] = __nv_bfloat162(
        __float2bfloat16(v.z - __bfloat162float(h2)),
        __float2bfloat16(v.w - __bfloat162float(h3)));
}

// ---------------- RMSNorm + bf16 split ----------------
__global__ void rmsnorm_split(const float* __restrict__ in, __nv_bfloat16* __restrict__ oh,
                              __nv_bfloat16* __restrict__ ol, const float* __restrict__ w,
                              int len, int in_stride)
{
    const int row = blockIdx.x;
    const float* ip = in + (size_t)row * in_stride;
    float ss = 0.f;
    for (int i = threadIdx.x; i < len; i += blockDim.x) {
        float v = ip[i];
        ss += v * v;
    }
    __shared__ float red[256];
    red[threadIdx.x] = ss;
    __syncthreads();
    #pragma unroll
    for (int s = 128; s > 0; s >>= 1) {
        if (threadIdx.x < s) red[threadIdx.x] += red[threadIdx.x + s];
        __syncthreads();
    }
    const float r = rsqrtf(red[0] / (float)len + 1e-6f);
    for (int i = threadIdx.x; i < len; i += blockDim.x) {
        float v = ip[i] * r;
        if (w) v *= w[i];
        __nv_bfloat16 h = __float2bfloat16(v);
        size_t o = (size_t)row * len + i;
        oh[o] = h;
        ol[o] = __float2bfloat16(v - __bfloat162float(h));
    }
}

// ---------------- RoPE on q (reshape quirk preserved) ----------------
__global__ void rope_q_kernel(float* __restrict__ q, const int* __restrict__ start_pos)
{
    int idx = blockIdx.x * blockDim.x + threadIdx.x;
    if (idx >= T_TOKENS * NH * 32) return;
    const int i = idx & 31;
    const int h = (idx >> 5) & 15;
    const int t = idx >> 9;
    const int s = t & (SEQ - 1);
    const int pos = ((s * NH + h) & (SEQ - 1)) + start_pos[0];

    const float theta = powf(10000.0f, -(float)i * (1.0f / 32.0f));
    const float ang = (float)pos * theta;
    float sn, cs;
    sincosf(ang, &sn, &cs);

    float* base = q + (size_t)t * QDIM + h * HD + DN;
    const float x1 = base[i];
    const float x2 = base[i + 32];
    base[i]      = x1 * cs - x2 * sn;
    base[i + 32] = x2 * cs + x1 * sn;
}

// ---------------- RoPE on k_pe (seq_len==1 quirk: pos = start_pos) ----------------
__global__ void rope_k_kernel(float* __restrict__ kv, const int* __restrict__ start_pos)
{
    int idx = blockIdx.x * blockDim.x + threadIdx.x;
    if (idx >= T_TOKENS * 32) return;
    const int i = idx & 31;
    const int t = idx >> 5;
    const int pos = start_pos[0];

    const float theta = powf(10000.0f, -(float)i * (1.0f / 32.0f));
    const float ang = (float)pos * theta;
    float sn, cs;
    sincosf(ang, &sn, &cs);

    float* base = kv + (size_t)t * KVA + KVL;
    const float x1 = base[i];
    const float x2 = base[i + 32];
    base[i]      = x1 * cs - x2 * sn;
    base[i + 32] = x2 * cs + x1 * sn;
}

// ---------------- per-token 16x16 attention, fused ctx bf16 split ----------------
__global__ __launch_bounds__(512)
void attn_kernel(const float* __restrict__ q, const float* __restrict__ kvup,
                 const float* __restrict__ kv,
                 __nv_bfloat16* __restrict__ ctx_h, __nv_bfloat16* __restrict__ ctx_l)
{
    const int t = blockIdx.x;
    __shared__ float ks[16][HD];
    __shared__ float vs[16][DV];

    const float* ku = kvup + (size_t)t * KVUPD;
    const float* pe = kv + (size_t)t * KVA + KVL;

    for (int idx = threadIdx.x; idx < 16 * 256; idx += blockDim.x) {
        const int kh = idx >> 8;
        const int c  = idx & 255;
        const float v = ku[idx];
        if (c < DN) ks[kh][c] = v;
        else        vs[kh][c - DN] = v;
    }
    for (int idx = threadIdx.x; idx < 16 * DR; idx += blockDim.x) {
        const int kh = idx >> 6;
        const int c  = idx & 63;
        ks[kh][DN + c] = pe[c];
    }
    __syncthreads();

    const int w    = threadIdx.x >> 5;
    const int lane = threadIdx.x & 31;
    const float* qr = q + (size_t)t * QDIM + w * HD;

    float qreg[6];
    #pragma unroll
    for (int e = 0; e < 6; e++) qreg[e] = qr[lane + 32 * e];

    float sc[16];
    #pragma unroll
    for (int kh = 0; kh < 16; kh++) {
        float p = 0.f;
        #pragma unroll
        for (int e = 0; e < 6; e++) p += qreg[e] * ks[kh][lane + 32 * e];
        #pragma unroll
        for (int o = 16; o > 0; o >>= 1) p += __shfl_xor_sync(0xffffffffu, p, o);
        sc[kh] = p * 0.07216878364870323f;   // 1/sqrt(192)
    }

    float m = sc[0];
    #pragma unroll
    for (int kh = 1; kh < 16; kh++) m = fmaxf(m, sc[kh]);
    float sum = 0.f;
    #pragma unroll
    for (int kh = 0; kh < 16; kh++) { sc[kh] = expf(sc[kh] - m); sum += sc[kh]; }
    const float inv = 1.f / sum;

    float acc[4] = {0.f, 0.f, 0.f, 0.f};
    #pragma unroll
    for (int kh = 0; kh < 16; kh++) {
        const float p = sc[kh] * inv;
        #pragma unroll
        for (int j = 0; j < 4; j++) acc[j] += p * vs[kh][lane + 32 * j];
    }

    const size_t ob = (size_t)t * (NH * DV) + w * DV;
    #pragma unroll
    for (int j = 0; j < 4; j++) {
        float v = acc[j];
        __nv_bfloat16 h = __float2bfloat16(v);
        ctx_h[ob + lane + 32 * j] = h;
        ctx_l[ob + lane + 32 * j] = __float2bfloat16(v - __bfloat162float(h));
    }
}

// ---------------- launcher ----------------
extern "C" void kernel_launch(void* const* d_in, const int* in_sizes, int n_in,
                              void* d_out, int out_size)
{
    const float* x        = (const float*)d_in[0];
    const float* wq_a     = (const float*)d_in[1];
    const float* q_norm_w = (const float*)d_in[2];
    const float* wq_b     = (const float*)d_in[3];
    const float* wkv_a    = (const float*)d_in[4];
    const float* wkv_b    = (const float*)d_in[5];
    const float* wo       = (const float*)d_in[6];
    const int*   start_pos = (const int*)d_in[7];
    float* out = (float*)d_out;

    float *qa, *qb, *kvb, *kvup;
    cudaGetSymbolAddress((void**)&qa,   g_qa);
    cudaGetSymbolAddress((void**)&qb,   g_q);
    cudaGetSymbolAddress((void**)&kvb,  g_kv);
    cudaGetSymbolAddress((void**)&kvup, g_kvup);

    __nv_bfloat16 *xs_h, *xs_l, *qan_h, *qan_l, *kvn_h, *kvn_l, *ctx_h, *ctx_l;
    cudaGetSymbolAddress((void**)&xs_h,  g_xs_h);  cudaGetSymbolAddress((void**)&xs_l,  g_xs_l);
    cudaGetSymbolAddress((void**)&qan_h, g_qan_h); cudaGetSymbolAddress((void**)&qan_l, g_qan_l);
    cudaGetSymbolAddress((void**)&kvn_h, g_kvn_h); cudaGetSymbolAddress((void**)&kvn_l, g_kvn_l);
    cudaGetSymbolAddress((void**)&ctx_h, g_ctx_h); cudaGetSymbolAddress((void**)&ctx_l, g_ctx_l);

    __nv_bfloat16 *wqa_h, *wqa_l, *wqb_h, *wqb_l, *wkva_h, *wkva_l, *wkvb_h, *wkvb_l, *wo_h, *wo_l;
    cudaGetSymbolAddress((void**)&wqa_h,  g_wqa_h);  cudaGetSymbolAddress((void**)&wqa_l,  g_wqa_l);
    cudaGetSymbolAddress((void**)&wqb_h,  g_wqb_h);  cudaGetSymbolAddress((void**)&wqb_l,  g_wqb_l);
    cudaGetSymbolAddress((void**)&wkva_h, g_wkva_h); cudaGetSymbolAddress((void**)&wkva_l, g_wkva_l);
    cudaGetSymbolAddress((void**)&wkvb_h, g_wkvb_h); cudaGetSymbolAddress((void**)&wkvb_l, g_wkvb_l);
    cudaGetSymbolAddress((void**)&wo_h,   g_wo_h);   cudaGetSymbolAddress((void**)&wo_l,   g_wo_l);

    cudaFuncSetAttribute(sgemm_mma, cudaFuncAttributeMaxDynamicSharedMemorySize, DYN_SMEM);

    const dim3 wsblk(32, 8);
    const int M = T_TOKENS;

    // weight transpose-splits (W[R][C] -> T[C][R])
    wsplit_T<<<dim3(QLORA/32, DIM/32),  wsblk>>>(wq_a,  wqa_h,  wqa_l,  DIM,   QLORA);
    wsplit_T<<<dim3(QDIM/32,  QLORA/32),wsblk>>>(wq_b,  wqb_h,  wqb_l,  QLORA, QDIM);
    wsplit_T<<<dim3(KVA/32,   DIM/32),  wsblk>>>(wkv_a, wkva_h, wkva_l, DIM,   KVA);
    wsplit_T<<<dim3(KVUPD/32, KVL/32),  wsblk>>>(wkv_b, wkvb_h, wkvb_l, KVL,   KVUPD);
    wsplit_T<<<dim3(DIM/32,   DIM/32),  wsblk>>>(wo,    wo_h,   wo_l,   DIM,   DIM);

    // x split
    {
        int n4 = (T_TOKENS * DIM) / 4;
        asplit<<<(n4 + 255) / 256, 256>>>(x, xs_h, xs_l, n4);
    }

    // 1) qa = x @ wq_a   [16384,2048]x[2048,1536]
    sgemm_mma<<<dim3(QLORA/BN, M/BM), 256, DYN_SMEM>>>(
        xs_h, xs_l, wqa_h, wqa_l, qa, M, QLORA, DIM);
    // 2) rmsnorm + split
    rmsnorm_split<<<T_TOKENS, 256>>>(qa, qan_h, qan_l, q_norm_w, QLORA, QLORA);
    // 3) q = qan @ wq_b  [16384,1536]x[1536,3072]
    sgemm_mma<<<dim3(QDIM/BN, M/BM), 256, DYN_SMEM>>>(
        qan_h, qan_l, wqb_h, wqb_l, qb, M, QDIM, QLORA);
    // 4) kv = x @ wkv_a  [16384,2048]x[2048,576]
    sgemm_mma<<<dim3((KVA + BN - 1)/BN, M/BM), 256, DYN_SMEM>>>(
        xs_h, xs_l, wkva_h, wkva_l, kvb, M, KVA, DIM);
    // 5) RoPE
    rope_q_kernel<<<(T_TOKENS * NH * 32 + 255) / 256, 256>>>(qb, start_pos);
    rope_k_kernel<<<(T_TOKENS * 32 + 255) / 256, 256>>>(kvb, start_pos);
    // 6) kv_c rmsnorm (weight = 1) + split
    rmsnorm_split<<<T_TOKENS, 256>>>(kvb, kvn_h, kvn_l, nullptr, KVL, KVA);
    // 7) kv_up = kvn @ wkv_b  [16384,512]x[512,4096]
    sgemm_mma<<<dim3(KVUPD/BN, M/BM), 256, DYN_SMEM>>>(
        kvn_h, kvn_l, wkvb_h, wkvb_l, kvup, M, KVUPD, KVL);
    // 8) per-token attention -> ctx (split)
    attn_kernel<<<T_TOKENS, 512>>>(qb, kvup, kvb, ctx_h, ctx_l);
    // 9) out = ctx @ wo  [16384,2048]x[2048,2048]
    sgemm_mma<<<dim3(DIM/BN, M/BM), 256, DYN_SMEM>>>(
        ctx_h, ctx_l, wo_h, wo_l, out, M, DIM, DIM);
}

// round 16
// speedup vs baseline: 2.6997x; 1.2891x over previous
#include <cuda_runtime.h>
#include <cuda_bf16.h>
#include <cstdint>

// ---------------- problem constants ----------------
#define T_TOKENS 16384      // b*s = 4*4096
#define SEQ      4096
#define DIM      2048
#define QLORA    1536
#define NH       16
#define DN       128
#define DR       64
#define DV       128
#define KVL      512
#define HD       192        // DN+DR
#define QDIM     3072       // NH*HD
#define KVA      576        // KVL+DR
#define KVUPD    4096       // NH*(DN+DV)

// ---------------- scratch (no allocs allowed) ----------------
__device__ float g_qa  [(size_t)T_TOKENS * QLORA];
__device__ float g_q   [(size_t)T_TOKENS * QDIM];
__device__ float g_kv  [(size_t)T_TOKENS * KVA];
__device__ float g_kvup[(size_t)T_TOKENS * KVUPD];

// bf16 split activations
__device__ __nv_bfloat16 g_xs_h [(size_t)T_TOKENS * DIM];
__device__ __nv_bfloat16 g_xs_l [(size_t)T_TOKENS * DIM];
__device__ __nv_bfloat16 g_qan_h[(size_t)T_TOKENS * QLORA];
__device__ __nv_bfloat16 g_qan_l[(size_t)T_TOKENS * QLORA];
__device__ __nv_bfloat16 g_kvn_h[(size_t)T_TOKENS * KVL];
__device__ __nv_bfloat16 g_kvn_l[(size_t)T_TOKENS * KVL];
__device__ __nv_bfloat16 g_ctx_h[(size_t)T_TOKENS * (NH * DV)];
__device__ __nv_bfloat16 g_ctx_l[(size_t)T_TOKENS * (NH * DV)];

// bf16 split weights, TRANSPOSED to [N][K]
__device__ __nv_bfloat16 g_wqa_h [(size_t)QLORA * DIM];
__device__ __nv_bfloat16 g_wqa_l [(size_t)QLORA * DIM];
__device__ __nv_bfloat16 g_wqb_h [(size_t)QDIM * QLORA];
__device__ __nv_bfloat16 g_wqb_l [(size_t)QDIM * QLORA];
__device__ __nv_bfloat16 g_wkva_h[(size_t)KVA * DIM];
__device__ __nv_bfloat16 g_wkva_l[(size_t)KVA * DIM];
__device__ __nv_bfloat16 g_wkvb_h[(size_t)KVUPD * KVL];
__device__ __nv_bfloat16 g_wkvb_l[(size_t)KVUPD * KVL];
__device__ __nv_bfloat16 g_wo_h  [(size_t)DIM * DIM];
__device__ __nv_bfloat16 g_wo_l  [(size_t)DIM * DIM];

// ---------------- PTX helpers (sm_80-compatible only) ----------------
__device__ __forceinline__ uint32_t smem_u32(const void* p) {
    uint32_t a;
    asm("{ .reg .u64 t; cvta.to.shared.u64 t, %1; cvt.u32.u64 %0, t; }"
        : "=r"(a) : "l"(p));
    return a;
}
__device__ __forceinline__ void cpa16(uint32_t dst, const void* src, int sz) {
    asm volatile("cp.async.cg.shared.global [%0], [%1], 16, %2;"
                 :: "r"(dst), "l"(src), "r"(sz));
}
__device__ __forceinline__ void ldm4(uint32_t* r, uint32_t a) {
    asm volatile("ldmatrix.sync.aligned.m8n8.x4.shared.b16 {%0,%1,%2,%3}, [%4];"
                 : "=r"(r[0]), "=r"(r[1]), "=r"(r[2]), "=r"(r[3]) : "r"(a));
}
__device__ __forceinline__ void mma16816(float* d, const uint32_t* a, const uint32_t* b) {
    asm volatile(
        "mma.sync.aligned.m16n8k16.row.col.f32.bf16.bf16.f32 "
        "{%0,%1,%2,%3}, {%4,%5,%6,%7}, {%8,%9}, {%0,%1,%2,%3};"
        : "+f"(d[0]), "+f"(d[1]), "+f"(d[2]), "+f"(d[3])
        : "r"(a[0]), "r"(a[1]), "r"(a[2]), "r"(a[3]), "r"(b[0]), "r"(b[1]));
}

// ---------------- HMMA GEMM ----------------
// C[M,N] fp32 = (Ah+Al)[M,K] @ (Bh+Bl)^T,  B arrays stored [N][K] bf16.
// 3-term compensated: Ah@Bh + Ah@Bl + Al@Bh, fp32 accumulators.
// CTA tile 128x128, BK=32, 8 warps (warp tile 64x32), 3-stage cp.async pipeline.
// Smem rows are 64B with XOR swizzle (no pad): conflict-free ldmatrix, and
// 3 stages fit in 96KB -> 2 CTAs/SM for latency hiding.
#define BM 128
#define BN 128
#define BK 32
#define MAT_BYTES (128 * 64)          // 8192 per matrix tile (64B rows, swizzled)
#define STAGE_BYTES (4 * MAT_BYTES)   // Ah|Al|Bh|Bl = 32768
#define STAGES 3
#define DYN_SMEM (STAGES * STAGE_BYTES)   // 98304

// swizzled byte offset of 16B chunk (row 0..127, chunk 0..3 within 64B row)
__device__ __forceinline__ uint32_t swz(int row, int chunk) {
    return (uint32_t)(row * 64 + ((chunk ^ ((row >> 1) & 3)) * 16));
}

__device__ __forceinline__ void stage_chunk(
    uint32_t sbase,
    const __nv_bfloat16* __restrict__ Ah, const __nv_bfloat16* __restrict__ Al,
    const __nv_bfloat16* __restrict__ Bh, const __nv_bfloat16* __restrict__ Bl,
    int m0, int n0, int N, int K, int k0, int tid)
{
    #pragma unroll
    for (int i = 0; i < 2; i++) {
        const int idx = tid + 256 * i;
        const int row = idx >> 2;
        const int kc  = idx & 3;
        const uint32_t off = swz(row, kc);
        const size_t ga = (size_t)(m0 + row) * K + k0 + kc * 8;
        cpa16(sbase + off,              Ah + ga, 16);
        cpa16(sbase + MAT_BYTES + off,  Al + ga, 16);
        const int n = n0 + row;
        const int sz = (n < N) ? 16 : 0;
        const size_t gb = (size_t)(n < N ? n : 0) * K + k0 + kc * 8;
        cpa16(sbase + 2 * MAT_BYTES + off, Bh + gb, sz);
        cpa16(sbase + 3 * MAT_BYTES + off, Bl + gb, sz);
    }
    asm volatile("cp.async.commit_group;");
}

__global__ __launch_bounds__(256, 2)
void sgemm_mma(const __nv_bfloat16* __restrict__ Ah, const __nv_bfloat16* __restrict__ Al,
               const __nv_bfloat16* __restrict__ Bh, const __nv_bfloat16* __restrict__ Bl,
               float* __restrict__ C, int M, int N, int K)
{
    extern __shared__ char dynsm[];
    const uint32_t sb = smem_u32(dynsm);

    const int tid  = threadIdx.x;
    const int wid  = tid >> 5;
    const int lane = tid & 31;
    const int m0 = blockIdx.y * BM;
    const int n0 = blockIdx.x * BN;

    const int warp_m = (wid >> 2) * 64;   // 0 or 64
    const int warp_n = (wid & 3) * 32;    // 0,32,64,96

    float acc[4][4][4];
    #pragma unroll
    for (int i = 0; i < 4; i++)
        #pragma unroll
        for (int j = 0; j < 4; j++)
            #pragma unroll
            for (int r = 0; r < 4; r++) acc[i][j][r] = 0.f;

    const int NC = K / BK;

    // prologue: stage chunks 0, 1
    stage_chunk(sb, Ah, Al, Bh, Bl, m0, n0, N, K, 0, tid);
    stage_chunk(sb + STAGE_BYTES, Ah, Al, Bh, Bl, m0, n0, N, K, BK, tid);

    // ldmatrix lane mapping
    const int a_row  = ((lane >> 3) & 1) * 8 + (lane & 7);  // 0..15
    const int a_chk  = lane >> 4;                           // 0..1
    const int b_row  = ((lane >> 4) & 1) * 8 + (lane & 7);  // 0..15
    const int b_chk  = (lane >> 3) & 1;                     // 0..1

    for (int c = 0; c < NC; ++c) {
        if (c < NC - 1) asm volatile("cp.async.wait_group 1;");
        else            asm volatile("cp.async.wait_group 0;");
        __syncthreads();

        if (c + 2 < NC)
            stage_chunk(sb + ((c + 2) % STAGES) * STAGE_BYTES,
                        Ah, Al, Bh, Bl, m0, n0, N, K, (c + 2) * BK, tid);

        const uint32_t st = sb + (c % STAGES) * STAGE_BYTES;

        #pragma unroll
        for (int ks = 0; ks < 2; ks++) {
            uint32_t fa_h[4][4], fa_l[4][4];
            #pragma unroll
            for (int i = 0; i < 4; i++) {
                const int row = warp_m + 16 * i + a_row;
                const uint32_t ad = st + swz(row, ks * 2 + a_chk);
                ldm4(fa_h[i], ad);
                ldm4(fa_l[i], ad + MAT_BYTES);
            }
            uint32_t fb_h[4][2], fb_l[4][2];
            #pragma unroll
            for (int jj = 0; jj < 2; jj++) {
                const int row = warp_n + 16 * jj + b_row;
                const uint32_t bd = st + 2 * MAT_BYTES + swz(row, ks * 2 + b_chk);
                uint32_t r[4];
                ldm4(r, bd);
                fb_h[2*jj][0] = r[0]; fb_h[2*jj][1] = r[1];
                fb_h[2*jj+1][0] = r[2]; fb_h[2*jj+1][1] = r[3];
                ldm4(r, bd + MAT_BYTES);
                fb_l[2*jj][0] = r[0]; fb_l[2*jj][1] = r[1];
                fb_l[2*jj+1][0] = r[2]; fb_l[2*jj+1][1] = r[3];
            }
            #pragma unroll
            for (int i = 0; i < 4; i++)
                #pragma unroll
                for (int j = 0; j < 4; j++) {
                    mma16816(acc[i][j], fa_h[i], fb_h[j]);
                    mma16816(acc[i][j], fa_h[i], fb_l[j]);
                    mma16816(acc[i][j], fa_l[i], fb_h[j]);
                }
        }
        __syncthreads();
    }

    // epilogue
    const int er = lane >> 2;
    const int ec = (lane & 3) * 2;
    #pragma unroll
    for (int i = 0; i < 4; i++) {
        const int row = m0 + warp_m + 16 * i + er;
        #pragma unroll
        for (int j = 0; j < 4; j++) {
            const int col = n0 + warp_n + 8 * j + ec;
            if (col < N) {
                float* cp0 = C + (size_t)row * N + col;
                *(float2*)cp0 = make_float2(acc[i][j][0], acc[i][j][1]);
                *(float2*)(cp0 + 8 * (size_t)N) = make_float2(acc[i][j][2], acc[i][j][3]);
            }
        }
    }
}

// ---------------- weight transpose + bf16 split ----------------
__global__ void wsplit_T(const float* __restrict__ W, __nv_bfloat16* __restrict__ Th,
                         __nv_bfloat16* __restrict__ Tl, int R, int Cc)
{
    __shared__ float t[32][33];
    const int c0 = blockIdx.x * 32, r0 = blockIdx.y * 32;
    const int tx = threadIdx.x, ty = threadIdx.y;   // 32 x 8
    #pragma unroll
    for (int i = 0; i < 32; i += 8)
        t[ty + i][tx] = W[(size_t)(r0 + ty + i) * Cc + c0 + tx];
    __syncthreads();
    #pragma unroll
    for (int i = 0; i < 32; i += 8) {
        float v = t[tx][ty + i];
        __nv_bfloat16 h = __float2bfloat16(v);
        __nv_bfloat16 l = __float2bfloat16(v - __bfloat162float(h));
        size_t o = (size_t)(c0 + ty + i) * R + r0 + tx;
        Th[o] = h; Tl[o] = l;
    }
}

// ---------------- activation bf16 split ----------------
__global__ void asplit(const float* __restrict__ src, __nv_bfloat16* __restrict__ h,
                       __nv_bfloat16* __restrict__ l, int n4)
{
    int i = blockIdx.x * blockDim.x + threadIdx.x;
    if (i >= n4) return;
    float4 v = ((const float4*)src)[i];
    __nv_bfloat16 h0 = __float2bfloat16(v.x), h1 = __float2bfloat16(v.y);
    __nv_bfloat16 h2 = __float2bfloat16(v.z), h3 = __float2bfloat16(v.w);
    ((__nv_bfloat162*)h)[2*i]   = __nv_bfloat162(h0, h1);
    ((__nv_bfloat162*)h)[2*i+1] = __nv_bfloat162(h2, h3);
    ((__nv_bfloat162*)l)[2*i]   = __nv_bfloat162(
        __float2bfloat16(v.x - __bfloat162float(h0)),
        __float2bfloat16(v.y - __bfloat162float(h1)));
    ((__nv_bfloat162*)l)[2*i+1] = __nv_bfloat162(
        __float2bfloat16(v.z - __bfloat162float(h2)),
        __float2bfloat16(v.w - __bfloat162float(h3)));
}

// ---------------- RMSNorm + bf16 split ----------------
__global__ void rmsnorm_split(const float* __restrict__ in, __nv_bfloat16* __restrict__ oh,
                              __nv_bfloat16* __restrict__ ol, const float* __restrict__ w,
                              int len, int in_stride)
{
    const int row = blockIdx.x;
    const float* ip = in + (size_t)row * in_stride;
    float ss = 0.f;
    for (int i = threadIdx.x; i < len; i += blockDim.x) {
        float v = ip[i];
        ss += v * v;
    }
    __shared__ float red[256];
    red[threadIdx.x] = ss;
    __syncthreads();
    #pragma unroll
    for (int s = 128; s > 0; s >>= 1) {
        if (threadIdx.x < s) red[threadIdx.x] += red[threadIdx.x + s];
        __syncthreads();
    }
    const float r = rsqrtf(red[0] / (float)len + 1e-6f);
    for (int i = threadIdx.x; i < len; i += blockDim.x) {
        float v = ip[i] * r;
        if (w) v *= w[i];
        __nv_bfloat16 h = __float2bfloat16(v);
        size_t o = (size_t)row * len + i;
        oh[o] = h;
        ol[o] = __float2bfloat16(v - __bfloat162float(h));
    }
}

// ---------------- RoPE on q (reshape quirk preserved) ----------------
__global__ void rope_q_kernel(float* __restrict__ q, const int* __restrict__ start_pos)
{
    int idx = blockIdx.x * blockDim.x + threadIdx.x;
    if (idx >= T_TOKENS * NH * 32) return;
    const int i = idx & 31;
    const int h = (idx >> 5) & 15;
    const int t = idx >> 9;
    const int s = t & (SEQ - 1);
    const int pos = ((s * NH + h) & (SEQ - 1)) + start_pos[0];

    const float theta = powf(10000.0f, -(float)i * (1.0f / 32.0f));
    const float ang = (float)pos * theta;
    float sn, cs;
    sincosf(ang, &sn, &cs);

    float* base = q + (size_t)t * QDIM + h * HD + DN;
    const float x1 = base[i];
    const float x2 = base[i + 32];
    base[i]      = x1 * cs - x2 * sn;
    base[i + 32] = x2 * cs + x1 * sn;
}

// ---------------- RoPE on k_pe (seq_len==1 quirk: pos = start_pos) ----------------
__global__ void rope_k_kernel(float* __restrict__ kv, const int* __restrict__ start_pos)
{
    int idx = blockIdx.x * blockDim.x + threadIdx.x;
    if (idx >= T_TOKENS * 32) return;
    const int i = idx & 31;
    const int t = idx >> 5;
    const int pos = start_pos[0];

    const float theta = powf(10000.0f, -(float)i * (1.0f / 32.0f));
    const float ang = (float)pos * theta;
    float sn, cs;
    sincosf(ang, &sn, &cs);

    float* base = kv + (size_t)t * KVA + KVL;
    const float x1 = base[i];
    const float x2 = base[i + 32];
    base[i]      = x1 * cs - x2 * sn;
    base[i + 32] = x2 * cs + x1 * sn;
}

// ---------------- per-token 16x16 attention, fused ctx bf16 split ----------------
__global__ __launch_bounds__(512)
void attn_kernel(const float* __restrict__ q, const float* __restrict__ kvup,
                 const float* __restrict__ kv,
                 __nv_bfloat16* __restrict__ ctx_h, __nv_bfloat16* __restrict__ ctx_l)
{
    const int t = blockIdx.x;
    __shared__ float ks[16][HD];
    __shared__ float vs[16][DV];

    const float* ku = kvup + (size_t)t * KVUPD;
    const float* pe = kv + (size_t)t * KVA + KVL;

    for (int idx = threadIdx.x; idx < 16 * 256; idx += blockDim.x) {
        const int kh = idx >> 8;
        const int c  = idx & 255;
        const float v = ku[idx];
        if (c < DN) ks[kh][c] = v;
        else        vs[kh][c - DN] = v;
    }
    for (int idx = threadIdx.x; idx < 16 * DR; idx += blockDim.x) {
        const int kh = idx >> 6;
        const int c  = idx & 63;
        ks[kh][DN + c] = pe[c];
    }
    __syncthreads();

    const int w    = threadIdx.x >> 5;
    const int lane = threadIdx.x & 31;
    const float* qr = q + (size_t)t * QDIM + w * HD;

    float qreg[6];
    #pragma unroll
    for (int e = 0; e < 6; e++) qreg[e] = qr[lane + 32 * e];

    float sc[16];
    #pragma unroll
    for (int kh = 0; kh < 16; kh++) {
        float p = 0.f;
        #pragma unroll
        for (int e = 0; e < 6; e++) p += qreg[e] * ks[kh][lane + 32 * e];
        #pragma unroll
        for (int o = 16; o > 0; o >>= 1) p += __shfl_xor_sync(0xffffffffu, p, o);
        sc[kh] = p * 0.07216878364870323f;   // 1/sqrt(192)
    }

    float m = sc[0];
    #pragma unroll
    for (int kh = 1; kh < 16; kh++) m = fmaxf(m, sc[kh]);
    float sum = 0.f;
    #pragma unroll
    for (int kh = 0; kh < 16; kh++) { sc[kh] = expf(sc[kh] - m); sum += sc[kh]; }
    const float inv = 1.f / sum;

    float acc[4] = {0.f, 0.f, 0.f, 0.f};
    #pragma unroll
    for (int kh = 0; kh < 16; kh++) {
        const float p = sc[kh] * inv;
        #pragma unroll
        for (int j = 0; j < 4; j++) acc[j] += p * vs[kh][lane + 32 * j];
    }

    const size_t ob = (size_t)t * (NH * DV) + w * DV;
    #pragma unroll
    for (int j = 0; j < 4; j++) {
        float v = acc[j];
        __nv_bfloat16 h = __float2bfloat16(v);
        ctx_h[ob + lane + 32 * j] = h;
        ctx_l[ob + lane + 32 * j] = __float2bfloat16(v - __bfloat162float(h));
    }
}

// ---------------- launcher ----------------
extern "C" void kernel_launch(void* const* d_in, const int* in_sizes, int n_in,
                              void* d_out, int out_size)
{
    const float* x        = (const float*)d_in[0];
    const float* wq_a     = (const float*)d_in[1];
    const float* q_norm_w = (const float*)d_in[2];
    const float* wq_b     = (const float*)d_in[3];
    const float* wkv_a    = (const float*)d_in[4];
    const float* wkv_b    = (const float*)d_in[5];
    const float* wo       = (const float*)d_in[6];
    const int*   start_pos = (const int*)d_in[7];
    float* out = (float*)d_out;

    float *qa, *qb, *kvb, *kvup;
    cudaGetSymbolAddress((void**)&qa,   g_qa);
    cudaGetSymbolAddress((void**)&qb,   g_q);
    cudaGetSymbolAddress((void**)&kvb,  g_kv);
    cudaGetSymbolAddress((void**)&kvup, g_kvup);

    __nv_bfloat16 *xs_h, *xs_l, *qan_h, *qan_l, *kvn_h, *kvn_l, *ctx_h, *ctx_l;
    cudaGetSymbolAddress((void**)&xs_h,  g_xs_h);  cudaGetSymbolAddress((void**)&xs_l,  g_xs_l);
    cudaGetSymbolAddress((void**)&qan_h, g_qan_h); cudaGetSymbolAddress((void**)&qan_l, g_qan_l);
    cudaGetSymbolAddress((void**)&kvn_h, g_kvn_h); cudaGetSymbolAddress((void**)&kvn_l, g_kvn_l);
    cudaGetSymbolAddress((void**)&ctx_h, g_ctx_h); cudaGetSymbolAddress((void**)&ctx_l, g_ctx_l);

    __nv_bfloat16 *wqa_h, *wqa_l, *wqb_h, *wqb_l, *wkva_h, *wkva_l, *wkvb_h, *wkvb_l, *wo_h, *wo_l;
    cudaGetSymbolAddress((void**)&wqa_h,  g_wqa_h);  cudaGetSymbolAddress((void**)&wqa_l,  g_wqa_l);
    cudaGetSymbolAddress((void**)&wqb_h,  g_wqb_h);  cudaGetSymbolAddress((void**)&wqb_l,  g_wqb_l);
    cudaGetSymbolAddress((void**)&wkva_h, g_wkva_h); cudaGetSymbolAddress((void**)&wkva_l, g_wkva_l);
    cudaGetSymbolAddress((void**)&wkvb_h, g_wkvb_h); cudaGetSymbolAddress((void**)&wkvb_l, g_wkvb_l);
    cudaGetSymbolAddress((void**)&wo_h,   g_wo_h);   cudaGetSymbolAddress((void**)&wo_l,   g_wo_l);

    cudaFuncSetAttribute(sgemm_mma, cudaFuncAttributeMaxDynamicSharedMemorySize, DYN_SMEM);

    const dim3 wsblk(32, 8);
    const int M = T_TOKENS;

    // weight transpose-splits (W[R][C] -> T[C][R])
    wsplit_T<<<dim3(QLORA/32, DIM/32),  wsblk>>>(wq_a,  wqa_h,  wqa_l,  DIM,   QLORA);
    wsplit_T<<<dim3(QDIM/32,  QLORA/32),wsblk>>>(wq_b,  wqb_h,  wqb_l,  QLORA, QDIM);
    wsplit_T<<<dim3(KVA/32,   DIM/32),  wsblk>>>(wkv_a, wkva_h, wkva_l, DIM,   KVA);
    wsplit_T<<<dim3(KVUPD/32, KVL/32),  wsblk>>>(wkv_b, wkvb_h, wkvb_l, KVL,   KVUPD);
    wsplit_T<<<dim3(DIM/32,   DIM/32),  wsblk>>>(wo,    wo_h,   wo_l,   DIM,   DIM);

    // x split
    {
        int n4 = (T_TOKENS * DIM) / 4;
        asplit<<<(n4 + 255) / 256, 256>>>(x, xs_h, xs_l, n4);
    }

    // 1) qa = x @ wq_a   [16384,2048]x[2048,1536]
    sgemm_mma<<<dim3(QLORA/BN, M/BM), 256, DYN_SMEM>>>(
        xs_h, xs_l, wqa_h, wqa_l, qa, M, QLORA, DIM);
    // 2) rmsnorm + split
    rmsnorm_split<<<T_TOKENS, 256>>>(qa, qan_h, qan_l, q_norm_w, QLORA, QLORA);
    // 3) q = qan @ wq_b  [16384,1536]x[1536,3072]
    sgemm_mma<<<dim3(QDIM/BN, M/BM), 256, DYN_SMEM>>>(
        qan_h, qan_l, wqb_h, wqb_l, qb, M, QDIM, QLORA);
    // 4) kv = x @ wkv_a  [16384,2048]x[2048,576]
    sgemm_mma<<<dim3((KVA + BN - 1)/BN, M/BM), 256, DYN_SMEM>>>(
        xs_h, xs_l, wkva_h, wkva_l, kvb, M, KVA, DIM);
    // 5) RoPE
    rope_q_kernel<<<(T_TOKENS * NH * 32 + 255) / 256, 256>>>(qb, start_pos);
    rope_k_kernel<<<(T_TOKENS * 32 + 255) / 256, 256>>>(kvb, start_pos);
    // 6) kv_c rmsnorm (weight = 1) + split
    rmsnorm_split<<<T_TOKENS, 256>>>(kvb, kvn_h, kvn_l, nullptr, KVL, KVA);
    // 7) kv_up = kvn @ wkv_b  [16384,512]x[512,4096]
    sgemm_mma<<<dim3(KVUPD/BN, M/BM), 256, DYN_SMEM>>>(
        kvn_h, kvn_l, wkvb_h, wkvb_l, kvup, M, KVUPD, KVL);
    // 8) per-token attention -> ctx (split)
    attn_kernel<<<T_TOKENS, 512>>>(qb, kvup, kvb, ctx_h, ctx_l);
    // 9) out = ctx @ wo  [16384,2048]x[2048,2048]
    sgemm_mma<<<dim3(DIM/BN, M/BM), 256, DYN_SMEM>>>(
        ctx_h, ctx_l, wo_h, wo_l, out, M, DIM, DIM);
}

// round 17
// speedup vs baseline: 2.7602x; 1.0224x over previous
#include <cuda_runtime.h>
#include <cuda_bf16.h>
#include <cstdint>

// ---------------- problem constants ----------------
#define T_TOKENS 16384      // b*s = 4*4096
#define SEQ      4096
#define DIM      2048
#define QLORA    1536
#define NH       16
#define DN       128
#define DR       64
#define DV       128
#define KVL      512
#define HD       192        // DN+DR
#define QDIM     3072       // NH*HD
#define KVA      576        // KVL+DR
#define KVUPD    4096       // NH*(DN+DV)

// ---------------- scratch (no allocs allowed) ----------------
__device__ float g_qa  [(size_t)T_TOKENS * QLORA];
__device__ float g_q   [(size_t)T_TOKENS * QDIM];
__device__ float g_kv  [(size_t)T_TOKENS * KVA];
__device__ float g_kvup[(size_t)T_TOKENS * KVUPD];

// bf16 split activations
__device__ __nv_bfloat16 g_xs_h [(size_t)T_TOKENS * DIM];
__device__ __nv_bfloat16 g_xs_l [(size_t)T_TOKENS * DIM];
__device__ __nv_bfloat16 g_qan_h[(size_t)T_TOKENS * QLORA];
__device__ __nv_bfloat16 g_qan_l[(size_t)T_TOKENS * QLORA];
__device__ __nv_bfloat16 g_kvn_h[(size_t)T_TOKENS * KVL];
__device__ __nv_bfloat16 g_kvn_l[(size_t)T_TOKENS * KVL];
__device__ __nv_bfloat16 g_ctx_h[(size_t)T_TOKENS * (NH * DV)];
__device__ __nv_bfloat16 g_ctx_l[(size_t)T_TOKENS * (NH * DV)];

// bf16 split weights, TRANSPOSED to [N][K]
__device__ __nv_bfloat16 g_wqa_h [(size_t)QLORA * DIM];
__device__ __nv_bfloat16 g_wqa_l [(size_t)QLORA * DIM];
__device__ __nv_bfloat16 g_wqb_h [(size_t)QDIM * QLORA];
__device__ __nv_bfloat16 g_wqb_l [(size_t)QDIM * QLORA];
__device__ __nv_bfloat16 g_wkva_h[(size_t)KVA * DIM];
__device__ __nv_bfloat16 g_wkva_l[(size_t)KVA * DIM];
__device__ __nv_bfloat16 g_wkvb_h[(size_t)KVUPD * KVL];
__device__ __nv_bfloat16 g_wkvb_l[(size_t)KVUPD * KVL];
__device__ __nv_bfloat16 g_wo_h  [(size_t)DIM * DIM];
__device__ __nv_bfloat16 g_wo_l  [(size_t)DIM * DIM];

// ---------------- PTX helpers (sm_80-compatible only) ----------------
__device__ __forceinline__ uint32_t smem_u32(const void* p) {
    uint32_t a;
    asm("{ .reg .u64 t; cvta.to.shared.u64 t, %1; cvt.u32.u64 %0, t; }"
        : "=r"(a) : "l"(p));
    return a;
}
__device__ __forceinline__ void cpa16(uint32_t dst, const void* src, int sz) {
    asm volatile("cp.async.cg.shared.global [%0], [%1], 16, %2;"
                 :: "r"(dst), "l"(src), "r"(sz));
}
__device__ __forceinline__ void ldm4(uint32_t* r, uint32_t a) {
    asm volatile("ldmatrix.sync.aligned.m8n8.x4.shared.b16 {%0,%1,%2,%3}, [%4];"
                 : "=r"(r[0]), "=r"(r[1]), "=r"(r[2]), "=r"(r[3]) : "r"(a));
}
__device__ __forceinline__ void mma16816(float* d, const uint32_t* a, const uint32_t* b) {
    asm volatile(
        "mma.sync.aligned.m16n8k16.row.col.f32.bf16.bf16.f32 "
        "{%0,%1,%2,%3}, {%4,%5,%6,%7}, {%8,%9}, {%0,%1,%2,%3};"
        : "+f"(d[0]), "+f"(d[1]), "+f"(d[2]), "+f"(d[3])
        : "r"(a[0]), "r"(a[1]), "r"(a[2]), "r"(a[3]), "r"(b[0]), "r"(b[1]));
}

// ---------------- HMMA GEMM ----------------
// C[M,N] fp32 = (Ah+Al)[M,K] @ (Bh+Bl)^T,  B arrays stored [N][K] bf16.
// 3-term compensated: Ah@Bh + Ah@Bl + Al@Bh, fp32 accumulators.
// CTA tile 128x128, BK=32, 8 warps (warp tile 64x32), 3-stage cp.async pipeline.
// 64B swizzled smem rows; 3 stages = 96KB -> 2 CTAs/SM. ONE barrier per chunk.
#define BM 128
#define BN 128
#define BK 32
#define MAT_BYTES (128 * 64)          // 8192 per matrix tile (64B rows, swizzled)
#define STAGE_BYTES (4 * MAT_BYTES)   // Ah|Al|Bh|Bl = 32768
#define STAGES 3
#define DYN_SMEM (STAGES * STAGE_BYTES)   // 98304

// swizzled byte offset of 16B chunk (row 0..127, chunk 0..3 within 64B row)
__device__ __forceinline__ uint32_t swz(int row, int chunk) {
    return (uint32_t)(row * 64 + ((chunk ^ ((row >> 1) & 3)) * 16));
}

__device__ __forceinline__ void stage_chunk(
    uint32_t sbase,
    const __nv_bfloat16* __restrict__ Ah, const __nv_bfloat16* __restrict__ Al,
    const __nv_bfloat16* __restrict__ Bh, const __nv_bfloat16* __restrict__ Bl,
    int m0, int n0, int N, int K, int k0, int tid)
{
    #pragma unroll
    for (int i = 0; i < 2; i++) {
        const int idx = tid + 256 * i;
        const int row = idx >> 2;
        const int kc  = idx & 3;
        const uint32_t off = swz(row, kc);
        const size_t ga = (size_t)(m0 + row) * K + k0 + kc * 8;
        cpa16(sbase + off,              Ah + ga, 16);
        cpa16(sbase + MAT_BYTES + off,  Al + ga, 16);
        const int n = n0 + row;
        const int sz = (n < N) ? 16 : 0;
        const size_t gb = (size_t)(n < N ? n : 0) * K + k0 + kc * 8;
        cpa16(sbase + 2 * MAT_BYTES + off, Bh + gb, sz);
        cpa16(sbase + 3 * MAT_BYTES + off, Bl + gb, sz);
    }
    asm volatile("cp.async.commit_group;");
}

__global__ __launch_bounds__(256, 2)
void sgemm_mma(const __nv_bfloat16* __restrict__ Ah, const __nv_bfloat16* __restrict__ Al,
               const __nv_bfloat16* __restrict__ Bh, const __nv_bfloat16* __restrict__ Bl,
               float* __restrict__ C, int M, int N, int K)
{
    extern __shared__ char dynsm[];
    const uint32_t sb = smem_u32(dynsm);

    const int tid  = threadIdx.x;
    const int wid  = tid >> 5;
    const int lane = tid & 31;
    const int m0 = blockIdx.y * BM;
    const int n0 = blockIdx.x * BN;

    const int warp_m = (wid >> 2) * 64;   // 0 or 64
    const int warp_n = (wid & 3) * 32;    // 0,32,64,96

    float acc[4][4][4];
    #pragma unroll
    for (int i = 0; i < 4; i++)
        #pragma unroll
        for (int j = 0; j < 4; j++)
            #pragma unroll
            for (int r = 0; r < 4; r++) acc[i][j][r] = 0.f;

    const int NC = K / BK;

    // prologue: stage chunks 0, 1
    stage_chunk(sb, Ah, Al, Bh, Bl, m0, n0, N, K, 0, tid);
    stage_chunk(sb + STAGE_BYTES, Ah, Al, Bh, Bl, m0, n0, N, K, BK, tid);

    // ldmatrix lane mapping
    const int a_row  = ((lane >> 3) & 1) * 8 + (lane & 7);  // 0..15
    const int a_chk  = lane >> 4;                           // 0..1
    const int b_row  = ((lane >> 4) & 1) * 8 + (lane & 7);  // 0..15
    const int b_chk  = (lane >> 3) & 1;                     // 0..1

    for (int c = 0; c < NC; ++c) {
        if (c < NC - 1) asm volatile("cp.async.wait_group 1;");
        else            asm volatile("cp.async.wait_group 0;");
        // single barrier per chunk: also orders reuse of stage (c-1)%3,
        // which the c+2 prefetch below overwrites.
        __syncthreads();

        if (c + 2 < NC)
            stage_chunk(sb + ((c + 2) % STAGES) * STAGE_BYTES,
                        Ah, Al, Bh, Bl, m0, n0, N, K, (c + 2) * BK, tid);

        const uint32_t st = sb + (c % STAGES) * STAGE_BYTES;

        #pragma unroll
        for (int ks = 0; ks < 2; ks++) {
            uint32_t fa_h[4][4], fa_l[4][4];
            #pragma unroll
            for (int i = 0; i < 4; i++) {
                const int row = warp_m + 16 * i + a_row;
                const uint32_t ad = st + swz(row, ks * 2 + a_chk);
                ldm4(fa_h[i], ad);
                ldm4(fa_l[i], ad + MAT_BYTES);
            }
            uint32_t fb_h[4][2], fb_l[4][2];
            #pragma unroll
            for (int jj = 0; jj < 2; jj++) {
                const int row = warp_n + 16 * jj + b_row;
                const uint32_t bd = st + 2 * MAT_BYTES + swz(row, ks * 2 + b_chk);
                uint32_t r[4];
                ldm4(r, bd);
                fb_h[2*jj][0] = r[0]; fb_h[2*jj][1] = r[1];
                fb_h[2*jj+1][0] = r[2]; fb_h[2*jj+1][1] = r[3];
                ldm4(r, bd + MAT_BYTES);
                fb_l[2*jj][0] = r[0]; fb_l[2*jj][1] = r[1];
                fb_l[2*jj+1][0] = r[2]; fb_l[2*jj+1][1] = r[3];
            }
            #pragma unroll
            for (int i = 0; i < 4; i++)
                #pragma unroll
                for (int j = 0; j < 4; j++) {
                    mma16816(acc[i][j], fa_h[i], fb_h[j]);
                    mma16816(acc[i][j], fa_h[i], fb_l[j]);
                    mma16816(acc[i][j], fa_l[i], fb_h[j]);
                }
        }
    }

    // epilogue
    const int er = lane >> 2;
    const int ec = (lane & 3) * 2;
    #pragma unroll
    for (int i = 0; i < 4; i++) {
        const int row = m0 + warp_m + 16 * i + er;
        #pragma unroll
        for (int j = 0; j < 4; j++) {
            const int col = n0 + warp_n + 8 * j + ec;
            if (col < N) {
                float* cp0 = C + (size_t)row * N + col;
                *(float2*)cp0 = make_float2(acc[i][j][0], acc[i][j][1]);
                *(float2*)(cp0 + 8 * (size_t)N) = make_float2(acc[i][j][2], acc[i][j][3]);
            }
        }
    }
}

// ---------------- all weight transpose+splits in ONE launch ----------------
// block ranges: wq_a 3072 | wq_b 4608 | wkv_a 1152 | wkv_b 2048 | wo 4096
__global__ void wsplit_all(
    const float* __restrict__ wq_a,  __nv_bfloat16* wqa_h,  __nv_bfloat16* wqa_l,
    const float* __restrict__ wq_b,  __nv_bfloat16* wqb_h,  __nv_bfloat16* wqb_l,
    const float* __restrict__ wkv_a, __nv_bfloat16* wkva_h, __nv_bfloat16* wkva_l,
    const float* __restrict__ wkv_b, __nv_bfloat16* wkvb_h, __nv_bfloat16* wkvb_l,
    const float* __restrict__ wo,    __nv_bfloat16* wo_h,   __nv_bfloat16* wo_l)
{
    int bid = blockIdx.x;
    const float* W; __nv_bfloat16 *Th, *Tl; int R, Cc, loc;
    if (bid < 3072)       { W = wq_a;  Th = wqa_h;  Tl = wqa_l;  R = DIM;  Cc = QLORA; loc = bid; }
    else if (bid < 7680)  { W = wq_b;  Th = wqb_h;  Tl = wqb_l;  R = QLORA; Cc = QDIM;  loc = bid - 3072; }
    else if (bid < 8832)  { W = wkv_a; Th = wkva_h; Tl = wkva_l; R = DIM;  Cc = KVA;   loc = bid - 7680; }
    else if (bid < 10880) { W = wkv_b; Th = wkvb_h; Tl = wkvb_l; R = KVL;  Cc = KVUPD; loc = bid - 8832; }
    else                  { W = wo;    Th = wo_h;   Tl = wo_l;   R = NH*DV; Cc = DIM;  loc = bid - 10880; }
    const int nCB = Cc / 32;
    const int c0 = (loc % nCB) * 32;
    const int r0 = (loc / nCB) * 32;

    __shared__ float t[32][33];
    const int tx = threadIdx.x, ty = threadIdx.y;   // 32 x 8
    #pragma unroll
    for (int i = 0; i < 32; i += 8)
        t[ty + i][tx] = W[(size_t)(r0 + ty + i) * Cc + c0 + tx];
    __syncthreads();
    #pragma unroll
    for (int i = 0; i < 32; i += 8) {
        float v = t[tx][ty + i];
        __nv_bfloat16 h = __float2bfloat16(v);
        __nv_bfloat16 l = __float2bfloat16(v - __bfloat162float(h));
        size_t o = (size_t)(c0 + ty + i) * R + r0 + tx;
        Th[o] = h; Tl[o] = l;
    }
}

// ---------------- activation bf16 split ----------------
__global__ void asplit(const float* __restrict__ src, __nv_bfloat16* __restrict__ h,
                       __nv_bfloat16* __restrict__ l, int n4)
{
    int i = blockIdx.x * blockDim.x + threadIdx.x;
    if (i >= n4) return;
    float4 v = ((const float4*)src)[i];
    __nv_bfloat16 h0 = __float2bfloat16(v.x), h1 = __float2bfloat16(v.y);
    __nv_bfloat16 h2 = __float2bfloat16(v.z), h3 = __float2bfloat16(v.w);
    ((__nv_bfloat162*)h)[2*i]   = __nv_bfloat162(h0, h1);
    ((__nv_bfloat162*)h)[2*i+1] = __nv_bfloat162(h2, h3);
    ((__nv_bfloat162*)l)[2*i]   = __nv_bfloat162(
        __float2bfloat16(v.x - __bfloat162float(h0)),
        __float2bfloat16(v.y - __bfloat162float(h1)));
    ((__nv_bfloat162*)l)[2*i+1] = __nv_bfloat162(
        __float2bfloat16(v.z - __bfloat162float(h2)),
        __float2bfloat16(v.w - __bfloat162float(h3)));
}

// ---------------- RMSNorm + bf16 split ----------------
__global__ void rmsnorm_split(const float* __restrict__ in, __nv_bfloat16* __restrict__ oh,
                              __nv_bfloat16* __restrict__ ol, const float* __restrict__ w,
                              int len, int in_stride)
{
    const int row = blockIdx.x;
    const float* ip = in + (size_t)row * in_stride;
    float ss = 0.f;
    for (int i = threadIdx.x; i < len; i += blockDim.x) {
        float v = ip[i];
        ss += v * v;
    }
    __shared__ float red[256];
    red[threadIdx.x] = ss;
    __syncthreads();
    #pragma unroll
    for (int s = 128; s > 0; s >>= 1) {
        if (threadIdx.x < s) red[threadIdx.x] += red[threadIdx.x + s];
        __syncthreads();
    }
    const float r = rsqrtf(red[0] / (float)len + 1e-6f);
    for (int i = threadIdx.x; i < len; i += blockDim.x) {
        float v = ip[i] * r;
        if (w) v *= w[i];
        __nv_bfloat16 h = __float2bfloat16(v);
        size_t o = (size_t)row * len + i;
        oh[o] = h;
        ol[o] = __float2bfloat16(v - __bfloat162float(h));
    }
}

// ---------------- per-token 16x16 attention with FUSED RoPE ----------------
// q rope quirk: reshape (b,s,h,dr)->(b,h,s,dr) => pos_q = ((s*16+h) mod 4096)+sp.
// k_pe rope quirk: seq_len==1 inside rope() => pos_k = sp for every token.
// k_pe is head-invariant => its score contribution is one dot product shared
// by all 16 key heads.
__global__ __launch_bounds__(512)
void attn_kernel(const float* __restrict__ q, const float* __restrict__ kvup,
                 const float* __restrict__ kv, const int* __restrict__ start_pos,
                 __nv_bfloat16* __restrict__ ctx_h, __nv_bfloat16* __restrict__ ctx_l)
{
    const int t = blockIdx.x;
    __shared__ float ks[16][DN];
    __shared__ float vs[16][DV];
    __shared__ float pe_rot[DR];

    const float* ku = kvup + (size_t)t * KVUPD;
    const float* pe = kv + (size_t)t * KVA + KVL;
    const int sp = start_pos[0];

    for (int idx = threadIdx.x; idx < 16 * 256; idx += 512) {
        const int kh = idx >> 8;
        const int c  = idx & 255;
        const float v = ku[idx];
        if (c < DN) ks[kh][c] = v;
        else        vs[kh][c - DN] = v;
    }
    if (threadIdx.x < 32) {
        const int i = threadIdx.x;
        const float theta = powf(10000.0f, -(float)i * (1.0f / 32.0f));
        float sn, cs;
        sincosf((float)sp * theta, &sn, &cs);
        const float x1 = pe[i], x2 = pe[i + 32];
        pe_rot[i]      = x1 * cs - x2 * sn;
        pe_rot[i + 32] = x2 * cs + x1 * sn;
    }
    __syncthreads();

    const int w    = threadIdx.x >> 5;
    const int lane = threadIdx.x & 31;
    const float* qr = q + (size_t)t * QDIM + w * HD;

    float qreg[4];
    #pragma unroll
    for (int e = 0; e < 4; e++) qreg[e] = qr[lane + 32 * e];

    // q rope in-register (pair = (lane, lane+32) of the rope block)
    const int s = t & (SEQ - 1);
    const int pos = ((s * NH + w) & (SEQ - 1)) + sp;
    const float theta = powf(10000.0f, -(float)lane * (1.0f / 32.0f));
    float sn, cs;
    sincosf((float)pos * theta, &sn, &cs);
    const float x1 = qr[DN + lane], x2 = qr[DN + 32 + lane];
    const float q4 = x1 * cs - x2 * sn;
    const float q5 = x2 * cs + x1 * sn;

    // shared pe dot (same for all kh)
    float pd = q4 * pe_rot[lane] + q5 * pe_rot[lane + 32];
    #pragma unroll
    for (int o = 16; o > 0; o >>= 1) pd += __shfl_xor_sync(0xffffffffu, pd, o);

    float sc[16];
    #pragma unroll
    for (int kh = 0; kh < 16; kh++) {
        float p = 0.f;
        #pragma unroll
        for (int e = 0; e < 4; e++) p += qreg[e] * ks[kh][lane + 32 * e];
        #pragma unroll
        for (int o = 16; o > 0; o >>= 1) p += __shfl_xor_sync(0xffffffffu, p, o);
        sc[kh] = (p + pd) * 0.07216878364870323f;   // 1/sqrt(192)
    }

    float m = sc[0];
    #pragma unroll
    for (int kh = 1; kh < 16; kh++) m = fmaxf(m, sc[kh]);
    float sum = 0.f;
    #pragma unroll
    for (int kh = 0; kh < 16; kh++) { sc[kh] = expf(sc[kh] - m); sum += sc[kh]; }
    const float inv = 1.f / sum;

    float acc[4] = {0.f, 0.f, 0.f, 0.f};
    #pragma unroll
    for (int kh = 0; kh < 16; kh++) {
        const float p = sc[kh] * inv;
        #pragma unroll
        for (int j = 0; j < 4; j++) acc[j] += p * vs[kh][lane + 32 * j];
    }

    const size_t ob = (size_t)t * (NH * DV) + w * DV;
    #pragma unroll
    for (int j = 0; j < 4; j++) {
        float v = acc[j];
        __nv_bfloat16 h = __float2bfloat16(v);
        ctx_h[ob + lane + 32 * j] = h;
        ctx_l[ob + lane + 32 * j] = __float2bfloat16(v - __bfloat162float(h));
    }
}

// ---------------- launcher ----------------
extern "C" void kernel_launch(void* const* d_in, const int* in_sizes, int n_in,
                              void* d_out, int out_size)
{
    const float* x        = (const float*)d_in[0];
    const float* wq_a     = (const float*)d_in[1];
    const float* q_norm_w = (const float*)d_in[2];
    const float* wq_b     = (const float*)d_in[3];
    const float* wkv_a    = (const float*)d_in[4];
    const float* wkv_b    = (const float*)d_in[5];
    const float* wo       = (const float*)d_in[6];
    const int*   start_pos = (const int*)d_in[7];
    float* out = (float*)d_out;

    float *qa, *qb, *kvb, *kvup;
    cudaGetSymbolAddress((void**)&qa,   g_qa);
    cudaGetSymbolAddress((void**)&qb,   g_q);
    cudaGetSymbolAddress((void**)&kvb,  g_kv);
    cudaGetSymbolAddress((void**)&kvup, g_kvup);

    __nv_bfloat16 *xs_h, *xs_l, *qan_h, *qan_l, *kvn_h, *kvn_l, *ctx_h, *ctx_l;
    cudaGetSymbolAddress((void**)&xs_h,  g_xs_h);  cudaGetSymbolAddress((void**)&xs_l,  g_xs_l);
    cudaGetSymbolAddress((void**)&qan_h, g_qan_h); cudaGetSymbolAddress((void**)&qan_l, g_qan_l);
    cudaGetSymbolAddress((void**)&kvn_h, g_kvn_h); cudaGetSymbolAddress((void**)&kvn_l, g_kvn_l);
    cudaGetSymbolAddress((void**)&ctx_h, g_ctx_h); cudaGetSymbolAddress((void**)&ctx_l, g_ctx_l);

    __nv_bfloat16 *wqa_h, *wqa_l, *wqb_h, *wqb_l, *wkva_h, *wkva_l, *wkvb_h, *wkvb_l, *wo_h, *wo_l;
    cudaGetSymbolAddress((void**)&wqa_h,  g_wqa_h);  cudaGetSymbolAddress((void**)&wqa_l,  g_wqa_l);
    cudaGetSymbolAddress((void**)&wqb_h,  g_wqb_h);  cudaGetSymbolAddress((void**)&wqb_l,  g_wqb_l);
    cudaGetSymbolAddress((void**)&wkva_h, g_wkva_h); cudaGetSymbolAddress((void**)&wkva_l, g_wkva_l);
    cudaGetSymbolAddress((void**)&wkvb_h, g_wkvb_h); cudaGetSymbolAddress((void**)&wkvb_l, g_wkvb_l);
    cudaGetSymbolAddress((void**)&wo_h,   g_wo_h);   cudaGetSymbolAddress((void**)&wo_l,   g_wo_l);

    cudaFuncSetAttribute(sgemm_mma, cudaFuncAttributeMaxDynamicSharedMemorySize, DYN_SMEM);

    const int M = T_TOKENS;

    // #1: all weight transpose-splits, one launch (14976 blocks)
    wsplit_all<<<14976, dim3(32, 8)>>>(
        wq_a, wqa_h, wqa_l, wq_b, wqb_h, wqb_l,
        wkv_a, wkva_h, wkva_l, wkv_b, wkvb_h, wkvb_l, wo, wo_h, wo_l);

    // #2: x split
    {
        int n4 = (T_TOKENS * DIM) / 4;
        asplit<<<(n4 + 255) / 256, 256>>>(x, xs_h, xs_l, n4);
    }

    // #3: qa = x @ wq_a   [16384,2048]x[2048,1536]
    sgemm_mma<<<dim3(QLORA/BN, M/BM), 256, DYN_SMEM>>>(
        xs_h, xs_l, wqa_h, wqa_l, qa, M, QLORA, DIM);
    // #4: rmsnorm + split
    rmsnorm_split<<<T_TOKENS, 256>>>(qa, qan_h, qan_l, q_norm_w, QLORA, QLORA);
    // #5: kv = x @ wkv_a  [16384,2048]x[2048,576]
    sgemm_mma<<<dim3((KVA + BN - 1)/BN, M/BM), 256, DYN_SMEM>>>(
        xs_h, xs_l, wkva_h, wkva_l, kvb, M, KVA, DIM);
    // #6 (ncu -s 5 captures this): q = qan @ wq_b  [16384,1536]x[1536,3072]
    sgemm_mma<<<dim3(QDIM/BN, M/BM), 256, DYN_SMEM>>>(
        qan_h, qan_l, wqb_h, wqb_l, qb, M, QDIM, QLORA);
    // #7: kv_c rmsnorm (weight = 1) + split
    rmsnorm_split<<<T_TOKENS, 256>>>(kvb, kvn_h, kvn_l, nullptr, KVL, KVA);
    // #8: kv_up = kvn @ wkv_b  [16384,512]x[512,4096]
    sgemm_mma<<<dim3(KVUPD/BN, M/BM), 256, DYN_SMEM>>>(
        kvn_h, kvn_l, wkvb_h, wkvb_l, kvup, M, KVUPD, KVL);
    // #9: per-token attention with fused RoPE -> ctx (split)
    attn_kernel<<<T_TOKENS, 512>>>(qb, kvup, kvb, start_pos, ctx_h, ctx_l);
    // #10: out = ctx @ wo  [16384,2048]x[2048,2048]
    sgemm_mma<<<dim3(DIM/BN, M/BM), 256, DYN_SMEM>>>(
        ctx_h, ctx_l, wo_h, wo_l, out, M, DIM, DIM);
}